// round 1
// baseline (speedup 1.0000x reference)
#include <cuda_runtime.h>
#include <math.h>

// Problem constants
#define BATCH 2
#define C 256
#define H 64
#define W 64
#define HW 4096        // H*W
#define K2 9
#define CO 256
#define CK 2304        // C*K2
#define G 4            // channel groups for conv partial sums
#define CPG 64         // channels per group

// Scratch (allocation-free rule: __device__ globals)
__device__ float g_part[BATCH * G * 27 * HW];   // [b][g][o(27)][p] partial conv sums
__device__ float g_v[BATCH * CK * HW];          // [b][c*9+k][p]  sampled im2col matrix

// ---------------------------------------------------------------------------
// Kernel 1: offset conv (18ch from residual) + modulator conv (9ch from x),
// partial over channel groups. One thread = (b, g, pixel), 27 accumulators.
// Weights staged in padded smem ([ci][o][12]) so each 9-tap row reads as
// 2x float4 + 1 float (aligned LDS128).
// ---------------------------------------------------------------------------
__global__ __launch_bounds__(256, 1)
void conv_offmod_kernel(const float* __restrict__ x,
                        const float* __restrict__ res,
                        const float* __restrict__ ow,   // [18][C][9]
                        const float* __restrict__ mw)   // [9][C][9]
{
    __shared__ __align__(16) float sw[32 * 27 * 12];    // 32 ch * 27 out * pad12

    const int tid  = threadIdx.x;
    const int bidx = blockIdx.x;          // B*G*16 = 128 blocks
    const int pblk = bidx & 15;
    const int g    = (bidx >> 4) & (G - 1);
    const int b    = bidx >> 6;
    const int p    = pblk * 256 + tid;
    const int h    = p >> 6;
    const int w    = p & 63;

    float acc[27];
#pragma unroll
    for (int o = 0; o < 27; ++o) acc[o] = 0.f;

    const float* xb = x   + (size_t)b * C * HW;
    const float* rb = res + (size_t)b * C * HW;

    for (int cc = 0; cc < 2; ++cc) {
        const int cbase = g * CPG + cc * 32;

        __syncthreads();
        // stage weights for 32 channels
        for (int i = tid; i < 32 * 243; i += 256) {
            const int ci = i / 243;
            const int t  = i % 243;
            const int c  = cbase + ci;
            const int o  = t / 9;
            const int tt = t % 9;
            float wv;
            if (o < 18) wv = ow[(size_t)o * CK + c * 9 + tt];
            else        wv = mw[(size_t)(o - 18) * CK + c * 9 + tt];
            sw[ci * 324 + o * 12 + tt] = wv;
        }
        __syncthreads();

        for (int ci = 0; ci < 32; ++ci) {
            const int c = cbase + ci;
            const float* xc = xb + (size_t)c * HW;
            const float* rc = rb + (size_t)c * HW;

            float rv[9], xv[9];
#pragma unroll
            for (int r = 0; r < 3; ++r) {
                const int hh = h + r - 1;
                const bool vy = ((unsigned)hh < 64u);
#pragma unroll
                for (int s = 0; s < 3; ++s) {
                    const int ww = w + s - 1;
                    const bool v = vy && ((unsigned)ww < 64u);
                    const int idx = hh * 64 + ww;
                    rv[r * 3 + s] = v ? rc[idx] : 0.f;
                    xv[r * 3 + s] = v ? xc[idx] : 0.f;
                }
            }

            const float* swc = sw + ci * 324;
#pragma unroll
            for (int o = 0; o < 18; ++o) {
                const float4 wA = *(const float4*)(swc + o * 12);
                const float4 wB = *(const float4*)(swc + o * 12 + 4);
                const float  wC = swc[o * 12 + 8];
                acc[o] += wA.x * rv[0] + wA.y * rv[1] + wA.z * rv[2] + wA.w * rv[3]
                        + wB.x * rv[4] + wB.y * rv[5] + wB.z * rv[6] + wB.w * rv[7]
                        + wC  * rv[8];
            }
#pragma unroll
            for (int o = 0; o < 9; ++o) {
                const float4 wA = *(const float4*)(swc + (18 + o) * 12);
                const float4 wB = *(const float4*)(swc + (18 + o) * 12 + 4);
                const float  wC = swc[(18 + o) * 12 + 8];
                acc[18 + o] += wA.x * xv[0] + wA.y * xv[1] + wA.z * xv[2] + wA.w * xv[3]
                             + wB.x * xv[4] + wB.y * xv[5] + wB.z * xv[6] + wB.w * xv[7]
                             + wC  * xv[8];
            }
        }
    }

    float* outp = g_part + (size_t)(b * G + g) * 27 * HW;
#pragma unroll
    for (int o = 0; o < 27; ++o) outp[o * HW + p] = acc[o];
}

// ---------------------------------------------------------------------------
// Kernel 2: combine partial conv sums -> offset (dy,dx) + modulator (sigmoid),
// then bilinear sample x into g_v[b][c*9+k][p]. Thread = (b, k, p).
// ---------------------------------------------------------------------------
__global__ __launch_bounds__(256, 4)
void sample_kernel(const float* __restrict__ x,
                   const float* __restrict__ ob,   // [18]
                   const float* __restrict__ mb)   // [9]
{
    const int tid = blockIdx.x * 256 + threadIdx.x;   // B*K2*HW = 73728
    const int p  = tid & (HW - 1);
    const int bk = tid >> 12;
    const int k  = bk % K2;
    const int b  = bk / K2;
    const int h  = p >> 6;
    const int w  = p & 63;

    const float* pb = g_part + (size_t)b * G * 27 * HW;
    float dy   = ob[2 * k];
    float dx   = ob[2 * k + 1];
    float mraw = mb[k];
#pragma unroll
    for (int g = 0; g < G; ++g) {
        dy   += pb[(g * 27 + 2 * k)     * HW + p];
        dx   += pb[(g * 27 + 2 * k + 1) * HW + p];
        mraw += pb[(g * 27 + 18 + k)    * HW + p];
    }
    const float m = 2.f / (1.f + expf(-mraw));

    const float py = dy + (float)(h - 1 + k / 3);
    const float px = dx + (float)(w - 1 + k % 3);
    const float y0f = floorf(py), x0f = floorf(px);
    const float wy1 = py - y0f,  wx1 = px - x0f;
    const float wy0 = 1.f - wy1, wx0 = 1.f - wx1;
    const int y0 = (int)y0f, x0 = (int)x0f;
    const int y1 = y0 + 1,   x1 = x0 + 1;

    int   l00, l01, l10, l11;
    float w00, w01, w10, w11;
    {
        bool v;
        int yc, xc;
        v = ((unsigned)y0 < 64u) && ((unsigned)x0 < 64u);
        yc = min(max(y0, 0), 63); xc = min(max(x0, 0), 63);
        l00 = yc * 64 + xc; w00 = v ? wy0 * wx0 * m : 0.f;
        v = ((unsigned)y0 < 64u) && ((unsigned)x1 < 64u);
        yc = min(max(y0, 0), 63); xc = min(max(x1, 0), 63);
        l01 = yc * 64 + xc; w01 = v ? wy0 * wx1 * m : 0.f;
        v = ((unsigned)y1 < 64u) && ((unsigned)x0 < 64u);
        yc = min(max(y1, 0), 63); xc = min(max(x0, 0), 63);
        l10 = yc * 64 + xc; w10 = v ? wy1 * wx0 * m : 0.f;
        v = ((unsigned)y1 < 64u) && ((unsigned)x1 < 64u);
        yc = min(max(y1, 0), 63); xc = min(max(x1, 0), 63);
        l11 = yc * 64 + xc; w11 = v ? wy1 * wx1 * m : 0.f;
    }

    const float* xb = x + (size_t)b * C * HW;
    float* vout = g_v + ((size_t)b * CK + k) * HW + p;   // stride per c: 9*HW
#pragma unroll 4
    for (int c = 0; c < C; ++c) {
        const float* xc = xb + (size_t)c * HW;
        const float val = w00 * xc[l00] + w01 * xc[l01]
                        + w10 * xc[l10] + w11 * xc[l11];
        vout[(size_t)c * 9 * HW] = val;
    }
}

// ---------------------------------------------------------------------------
// Kernel 3: SGEMM  out[b][o][p] = sum_ck W[o][ck] * V[b][ck][p]
// M=256, K=2304, N=4096 per batch. 128x128 tile, BK=8, 8x8 per thread.
// ---------------------------------------------------------------------------
#define BM 128
#define BN 128
#define BK 8

__global__ __launch_bounds__(256, 1)
void gemm_kernel(const float* __restrict__ A,   // [CO][CK] = reg_w
                 float* __restrict__ out)       // [BATCH][CO][HW]
{
    __shared__ __align__(16) float As[BK][BM];
    __shared__ __align__(16) float Bs[BK][BN];

    const int b  = blockIdx.z;
    const float* Bv = g_v + (size_t)b * CK * HW;
    const int m0 = blockIdx.y * BM;
    const int n0 = blockIdx.x * BN;
    const int tid = threadIdx.x;

    const int am = tid >> 1;                 // 0..127
    const int ak = (tid & 1) * 4;            // 0 or 4
    const int bk = tid >> 5;                 // 0..7
    const int bn = (tid & 31) * 4;           // 0..124
    const int tx = tid & 15;
    const int ty = tid >> 4;

    float accm[8][8];
#pragma unroll
    for (int i = 0; i < 8; ++i)
#pragma unroll
        for (int j = 0; j < 8; ++j) accm[i][j] = 0.f;

    for (int k0 = 0; k0 < CK; k0 += BK) {
        const float4 a4 = *(const float4*)(A + (size_t)(m0 + am) * CK + k0 + ak);
        As[ak + 0][am] = a4.x;
        As[ak + 1][am] = a4.y;
        As[ak + 2][am] = a4.z;
        As[ak + 3][am] = a4.w;
        const float4 b4 = *(const float4*)(Bv + (size_t)(k0 + bk) * HW + n0 + bn);
        *(float4*)&Bs[bk][bn] = b4;
        __syncthreads();

#pragma unroll
        for (int kk = 0; kk < BK; ++kk) {
            const float4 a0 = *(const float4*)&As[kk][ty * 8];
            const float4 a1 = *(const float4*)&As[kk][ty * 8 + 4];
            const float4 b0 = *(const float4*)&Bs[kk][tx * 8];
            const float4 b1 = *(const float4*)&Bs[kk][tx * 8 + 4];
            const float ar[8] = {a0.x, a0.y, a0.z, a0.w, a1.x, a1.y, a1.z, a1.w};
            const float br[8] = {b0.x, b0.y, b0.z, b0.w, b1.x, b1.y, b1.z, b1.w};
#pragma unroll
            for (int i = 0; i < 8; ++i)
#pragma unroll
                for (int j = 0; j < 8; ++j)
                    accm[i][j] += ar[i] * br[j];
        }
        __syncthreads();
    }

    float* ob = out + ((size_t)b * CO + m0) * HW + n0;
#pragma unroll
    for (int i = 0; i < 8; ++i) {
#pragma unroll
        for (int j = 0; j < 8; j += 4) {
            float4 v;
            v.x = accm[i][j];
            v.y = accm[i][j + 1];
            v.z = accm[i][j + 2];
            v.w = accm[i][j + 3];
            *(float4*)(ob + (size_t)(ty * 8 + i) * HW + tx * 8 + j) = v;
        }
    }
}

// ---------------------------------------------------------------------------
extern "C" void kernel_launch(void* const* d_in, const int* in_sizes, int n_in,
                              void* d_out, int out_size)
{
    const float* x   = (const float*)d_in[0];   // [2,256,64,64]
    const float* res = (const float*)d_in[1];   // [2,256,64,64]
    const float* ow  = (const float*)d_in[2];   // [18,256,3,3]
    const float* ob  = (const float*)d_in[3];   // [18]
    const float* mw  = (const float*)d_in[4];   // [9,256,3,3]
    const float* mb  = (const float*)d_in[5];   // [9]
    const float* rw  = (const float*)d_in[6];   // [256,256,3,3]
    float* out = (float*)d_out;                 // [2,256,64,64]

    conv_offmod_kernel<<<128, 256>>>(x, res, ow, mw);
    sample_kernel<<<288, 256>>>(x, ob, mb);
    gemm_kernel<<<dim3(HW / BN, CO / BM, BATCH), 256>>>(rw, out);
}

// round 3
// speedup vs baseline: 1.6644x; 1.6644x over previous
#include <cuda_runtime.h>
#include <cstdint>
#include <math.h>

// Problem constants
#define BATCH 2
#define C 256
#define H 64
#define W 64
#define HW 4096
#define K2 9
#define CO 256
#define CK 2304        // C*K2
#define G 4            // channel groups for conv partial sums

// Scratch (__device__ globals; allocation-free rule)
__device__ float g_part[BATCH * G * 27 * HW];     // [b][g][o(27)][p]
__device__ float g_v[(size_t)BATCH * HW * CK];    // [b][p][ck] K-major, tf32-rounded
__device__ float g_wt[(size_t)CO * CK];           // W tf32-rounded

// ---------------------------------------------------------------------------
// helpers
// ---------------------------------------------------------------------------
__device__ __forceinline__ uint32_t smem_u32(const void* p) {
    uint32_t a;
    asm("{ .reg .u64 t; cvta.to.shared.u64 t, %1; cvt.u32.u64 %0, t; }" : "=r"(a) : "l"(p));
    return a;
}
__device__ __forceinline__ void cp_async16(uint32_t dst, const void* src) {
    asm volatile("cp.async.cg.shared.global [%0], [%1], 16;" :: "r"(dst), "l"(src));
}
#define CP_COMMIT() asm volatile("cp.async.commit_group;" ::: "memory")
#define CP_WAIT(n)  asm volatile("cp.async.wait_group %0;" :: "n"(n) : "memory")

__device__ __forceinline__ float tf32r(float x) {
    uint32_t r;
    asm("cvt.rna.tf32.f32 %0, %1;" : "=r"(r) : "f"(x));
    return __uint_as_float(r);
}
__device__ __forceinline__ void mma1688(float c[4], const uint32_t a[4], const uint32_t b[2]) {
    asm volatile(
        "mma.sync.aligned.m16n8k8.row.col.f32.tf32.tf32.f32 "
        "{%0,%1,%2,%3}, {%4,%5,%6,%7}, {%8,%9}, {%0,%1,%2,%3};"
        : "+f"(c[0]), "+f"(c[1]), "+f"(c[2]), "+f"(c[3])
        : "r"(a[0]), "r"(a[1]), "r"(a[2]), "r"(a[3]), "r"(b[0]), "r"(b[1]));
}

// ---------------------------------------------------------------------------
// Kernel 0: round reg_w to tf32 into g_wt
// ---------------------------------------------------------------------------
__global__ __launch_bounds__(256)
void prep_w_kernel(const float* __restrict__ w)
{
    const int i = blockIdx.x * 256 + threadIdx.x;   // CO*CK/4 = 147456
    float4 v = ((const float4*)w)[i];
    v.x = tf32r(v.x); v.y = tf32r(v.y); v.z = tf32r(v.z); v.w = tf32r(v.w);
    ((float4*)g_wt)[i] = v;
}

// ---------------------------------------------------------------------------
// Kernel 1: offset conv (18ch from residual) + mod conv (9ch from x),
// partial over G=4 channel groups. 128-thread blocks, 256 blocks.
// ---------------------------------------------------------------------------
__global__ __launch_bounds__(128)
void conv_offmod_kernel(const float* __restrict__ x,
                        const float* __restrict__ res,
                        const float* __restrict__ ow,   // [18][C][9]
                        const float* __restrict__ mw)   // [9][C][9]
{
    __shared__ __align__(16) float sw[32 * 27 * 12];

    const int tid  = threadIdx.x;
    const int bidx = blockIdx.x;          // B*G*32 = 256 blocks
    const int pblk = bidx & 31;
    const int g    = (bidx >> 5) & (G - 1);
    const int b    = bidx >> 7;
    const int p    = pblk * 128 + tid;
    const int h    = p >> 6;
    const int w    = p & 63;

    float acc[27];
#pragma unroll
    for (int o = 0; o < 27; ++o) acc[o] = 0.f;

    const float* xb = x   + (size_t)b * C * HW;
    const float* rb = res + (size_t)b * C * HW;

    for (int cc = 0; cc < 2; ++cc) {
        const int cbase = g * 64 + cc * 32;

        __syncthreads();
        for (int i = tid; i < 32 * 243; i += 128) {
            const int ci = i / 243;
            const int t  = i % 243;
            const int c  = cbase + ci;
            const int o  = t / 9;
            const int tt = t % 9;
            float wv;
            if (o < 18) wv = ow[(size_t)o * CK + c * 9 + tt];
            else        wv = mw[(size_t)(o - 18) * CK + c * 9 + tt];
            sw[ci * 324 + o * 12 + tt] = wv;
        }
        __syncthreads();

        for (int ci = 0; ci < 32; ++ci) {
            const int c = cbase + ci;
            const float* xc = xb + (size_t)c * HW;
            const float* rc = rb + (size_t)c * HW;

            float rv[9], xv[9];
#pragma unroll
            for (int r = 0; r < 3; ++r) {
                const int hh = h + r - 1;
                const bool vy = ((unsigned)hh < 64u);
#pragma unroll
                for (int s = 0; s < 3; ++s) {
                    const int ww = w + s - 1;
                    const bool v = vy && ((unsigned)ww < 64u);
                    const int idx = hh * 64 + ww;
                    rv[r * 3 + s] = v ? rc[idx] : 0.f;
                    xv[r * 3 + s] = v ? xc[idx] : 0.f;
                }
            }

            const float* swc = sw + ci * 324;
#pragma unroll
            for (int o = 0; o < 18; ++o) {
                const float4 wA = *(const float4*)(swc + o * 12);
                const float4 wB = *(const float4*)(swc + o * 12 + 4);
                const float  wC = swc[o * 12 + 8];
                acc[o] += wA.x * rv[0] + wA.y * rv[1] + wA.z * rv[2] + wA.w * rv[3]
                        + wB.x * rv[4] + wB.y * rv[5] + wB.z * rv[6] + wB.w * rv[7]
                        + wC  * rv[8];
            }
#pragma unroll
            for (int o = 0; o < 9; ++o) {
                const float4 wA = *(const float4*)(swc + (18 + o) * 12);
                const float4 wB = *(const float4*)(swc + (18 + o) * 12 + 4);
                const float  wC = swc[(18 + o) * 12 + 8];
                acc[18 + o] += wA.x * xv[0] + wA.y * xv[1] + wA.z * xv[2] + wA.w * xv[3]
                             + wB.x * xv[4] + wB.y * xv[5] + wB.z * xv[6] + wB.w * xv[7]
                             + wC  * xv[8];
            }
        }
    }

    float* outp = g_part + (size_t)(b * G + g) * 27 * HW;
#pragma unroll
    for (int o = 0; o < 27; ++o) outp[o * HW + p] = acc[o];
}

// ---------------------------------------------------------------------------
// Kernel 2: combine partials -> coords/weights, bilinear-sample x into
// g_v[b][p][ck] (ck-contiguous, tf32-rounded).
// ---------------------------------------------------------------------------
#define PTILE 32
__global__ __launch_bounds__(256)
void sample_kernel(const float* __restrict__ x,
                   const float* __restrict__ ob,   // [18]
                   const float* __restrict__ mb)   // [9]
{
    __shared__ int   sl0[PTILE * 9], sl1[PTILE * 9], sl2[PTILE * 9], sl3[PTILE * 9];
    __shared__ float sw0[PTILE * 9], sw1[PTILE * 9], sw2[PTILE * 9], sw3[PTILE * 9];
    __shared__ float sv[PTILE][289];   // odd stride: conflict-free both phases

    const int tid  = threadIdx.x;
    const int lane = tid & 31;
    const int wid  = tid >> 5;
    const int b    = blockIdx.y;
    const int p0   = blockIdx.x * PTILE;

    for (int i = tid; i < PTILE * 9; i += 256) {
        const int pi = i / 9;
        const int k  = i - pi * 9;
        const int p  = p0 + pi;
        const int h  = p >> 6;
        const int w  = p & 63;

        const float* pb = g_part + (size_t)b * G * 27 * HW;
        float dy   = ob[2 * k];
        float dx   = ob[2 * k + 1];
        float mraw = mb[k];
#pragma unroll
        for (int g = 0; g < G; ++g) {
            dy   += pb[(g * 27 + 2 * k)     * HW + p];
            dx   += pb[(g * 27 + 2 * k + 1) * HW + p];
            mraw += pb[(g * 27 + 18 + k)    * HW + p];
        }
        const float m = 2.f / (1.f + expf(-mraw));

        const float py = dy + (float)(h - 1 + k / 3);
        const float px = dx + (float)(w - 1 + k % 3);
        const float y0f = floorf(py), x0f = floorf(px);
        const float wy1 = py - y0f,  wx1 = px - x0f;
        const float wy0 = 1.f - wy1, wx0 = 1.f - wx1;
        const int y0 = (int)y0f, x0 = (int)x0f;
        const int y1 = y0 + 1,   x1 = x0 + 1;

        bool v; int yc, xc;
        v = ((unsigned)y0 < 64u) && ((unsigned)x0 < 64u);
        yc = min(max(y0, 0), 63); xc = min(max(x0, 0), 63);
        sl0[i] = yc * 64 + xc; sw0[i] = v ? wy0 * wx0 * m : 0.f;
        v = ((unsigned)y0 < 64u) && ((unsigned)x1 < 64u);
        yc = min(max(y0, 0), 63); xc = min(max(x1, 0), 63);
        sl1[i] = yc * 64 + xc; sw1[i] = v ? wy0 * wx1 * m : 0.f;
        v = ((unsigned)y1 < 64u) && ((unsigned)x0 < 64u);
        yc = min(max(y1, 0), 63); xc = min(max(x0, 0), 63);
        sl2[i] = yc * 64 + xc; sw2[i] = v ? wy1 * wx0 * m : 0.f;
        v = ((unsigned)y1 < 64u) && ((unsigned)x1 < 64u);
        yc = min(max(y1, 0), 63); xc = min(max(x1, 0), 63);
        sl3[i] = yc * 64 + xc; sw3[i] = v ? wy1 * wx1 * m : 0.f;
    }
    __syncthreads();

    const float* xb = x + (size_t)b * C * HW;

    for (int c0 = 0; c0 < C; c0 += 32) {
        // Phase A: gather (lane = p index; p-adjacent addresses -> L2 locality)
#pragma unroll 4
        for (int pair = wid; pair < 288; pair += 8) {
            const int cl = pair / 9;
            const int k  = pair - cl * 9;
            const int idx = lane * 9 + k;
            const float* xc = xb + (size_t)(c0 + cl) * HW;
            const float val = sw0[idx] * __ldg(xc + sl0[idx])
                            + sw1[idx] * __ldg(xc + sl1[idx])
                            + sw2[idx] * __ldg(xc + sl2[idx])
                            + sw3[idx] * __ldg(xc + sl3[idx]);
            sv[lane][pair] = tf32r(val);
        }
        __syncthreads();

        // Phase B: coalesced write-out
#pragma unroll
        for (int pass = 0; pass < 4; ++pass) {
            const int pi = wid * 4 + pass;
            float* dst = g_v + ((size_t)(b * HW + p0 + pi)) * CK + c0 * 9;
#pragma unroll
            for (int i = 0; i < 9; ++i)
                dst[lane + 32 * i] = sv[pi][lane + 32 * i];
        }
        __syncthreads();
    }
}

// ---------------------------------------------------------------------------
// Kernel 3: tf32 mma.sync GEMM.
//   out[b][o][p] = sum_ck W[o][ck] * V[b][p][ck]
// A = g_wt rows o (row-major MxK), B = g_v rows p ("col-major" KxN = N rows
// of K), both K-major. Block tile 128(o) x 128(p), BK=32, 3-stage cp.async.
// 8 warps, each 64x32 via m16n8k8 (4 m-tiles x 4 n-tiles).
// ---------------------------------------------------------------------------
#define BK 32
#define PADK 36                  // smem row stride in floats
#define STG_FLOATS (128 * PADK)  // 4608 floats per tile
#define STAGE_FLOATS (2 * STG_FLOATS)
#define NSTAGE 3
#define NCH (CK / BK)            // 72
#define GEMM_SMEM (NSTAGE * STAGE_FLOATS * 4)   // 110592 B

__global__ __launch_bounds__(256)
void gemm_mma_kernel(float* __restrict__ out)
{
    extern __shared__ float sm[];
    const uint32_t sb = smem_u32(sm);

    const int tid  = threadIdx.x;
    const int lane = tid & 31;
    const int wid  = tid >> 5;
    const int b    = blockIdx.z;
    const int m0   = blockIdx.y * 128;   // o
    const int n0   = blockIdx.x * 128;   // p

    const float* gA = g_wt + (size_t)m0 * CK;
    const float* gB = g_v  + ((size_t)(b * HW + n0)) * CK;

    // loader mapping: row = tid>>1 (0..127), half-row 16 floats per thread
    const int lr = tid >> 1;
    const int lc = (tid & 1) * 16;
    const float* pa = gA + (size_t)lr * CK + lc;
    const float* pb = gB + (size_t)lr * CK + lc;
    const uint32_t da0 = sb + (uint32_t)(lr * PADK + lc) * 4;

#define LOAD_TILE(stage, ch) do {                                             \
        const uint32_t _dA = da0 + (stage) * STAGE_FLOATS * 4;                \
        const uint32_t _dB = _dA + STG_FLOATS * 4;                            \
        const float* _pa = pa + (ch) * BK;                                    \
        const float* _pb = pb + (ch) * BK;                                    \
        cp_async16(_dA,      _pa);                                            \
        cp_async16(_dA + 16, _pa + 4);                                        \
        cp_async16(_dA + 32, _pa + 8);                                        \
        cp_async16(_dA + 48, _pa + 12);                                       \
        cp_async16(_dB,      _pb);                                            \
        cp_async16(_dB + 16, _pb + 4);                                        \
        cp_async16(_dB + 32, _pb + 8);                                        \
        cp_async16(_dB + 48, _pb + 12);                                       \
    } while (0)

    float c[16][4];
#pragma unroll
    for (int i = 0; i < 16; ++i)
#pragma unroll
        for (int j = 0; j < 4; ++j) c[i][j] = 0.f;

    const int wm = (wid >> 2) * 64;     // warp m offset (o)
    const int wn = (wid & 3) * 32;      // warp n offset (p)
    const int qr = lane >> 2;
    const int qc = lane & 3;

    LOAD_TILE(0, 0); CP_COMMIT();
    LOAD_TILE(1, 1); CP_COMMIT();

    int stage = 0;
    for (int ch = 0; ch < NCH; ++ch) {
        if (ch + 2 < NCH) {
            const int ns = (stage + 2 >= NSTAGE) ? stage + 2 - NSTAGE : stage + 2;
            LOAD_TILE(ns, ch + 2);
        }
        CP_COMMIT();
        CP_WAIT(2);
        __syncthreads();

        const float* Ab = sm + stage * STAGE_FLOATS;
        const float* Bb = Ab + STG_FLOATS;

#pragma unroll
        for (int k8 = 0; k8 < BK / 8; ++k8) {
            const int ac = k8 * 8 + qc;
            uint32_t a[4][4], bb[4][2];
#pragma unroll
            for (int mt = 0; mt < 4; ++mt) {
                const float* ap = Ab + (wm + mt * 16 + qr) * PADK + ac;
                a[mt][0] = __float_as_uint(ap[0]);
                a[mt][1] = __float_as_uint(ap[8 * PADK]);
                a[mt][2] = __float_as_uint(ap[4]);
                a[mt][3] = __float_as_uint(ap[8 * PADK + 4]);
            }
#pragma unroll
            for (int nt = 0; nt < 4; ++nt) {
                const float* bp = Bb + (wn + nt * 8 + qr) * PADK + ac;
                bb[nt][0] = __float_as_uint(bp[0]);
                bb[nt][1] = __float_as_uint(bp[4]);
            }
#pragma unroll
            for (int mt = 0; mt < 4; ++mt)
#pragma unroll
                for (int nt = 0; nt < 4; ++nt)
                    mma1688(c[mt * 4 + nt], a[mt], bb[nt]);
        }
        __syncthreads();
        stage = (stage + 1 >= NSTAGE) ? 0 : stage + 1;
    }

    // epilogue: c frag (m16n8): c0,c1 -> row qr, cols 2qc,2qc+1 ; c2,c3 -> row qr+8
#pragma unroll
    for (int mt = 0; mt < 4; ++mt) {
#pragma unroll
        for (int nt = 0; nt < 4; ++nt) {
            const int o  = m0 + wm + mt * 16 + qr;
            const int p  = n0 + wn + nt * 8 + 2 * qc;
            float* o0 = out + ((size_t)(b * CO + o)) * HW + p;
            float2 v0; v0.x = c[mt * 4 + nt][0]; v0.y = c[mt * 4 + nt][1];
            *(float2*)o0 = v0;
            float2 v1; v1.x = c[mt * 4 + nt][2]; v1.y = c[mt * 4 + nt][3];
            *(float2*)(o0 + 8 * HW) = v1;
        }
    }
}

// ---------------------------------------------------------------------------
extern "C" void kernel_launch(void* const* d_in, const int* in_sizes, int n_in,
                              void* d_out, int out_size)
{
    const float* x   = (const float*)d_in[0];   // [2,256,64,64]
    const float* res = (const float*)d_in[1];   // [2,256,64,64]
    const float* ow  = (const float*)d_in[2];   // [18,256,3,3]
    const float* ob  = (const float*)d_in[3];   // [18]
    const float* mw  = (const float*)d_in[4];   // [9,256,3,3]
    const float* mb  = (const float*)d_in[5];   // [9]
    const float* rw  = (const float*)d_in[6];   // [256,256,3,3]
    float* out = (float*)d_out;                 // [2,256,64,64]

    static int smem_set = 0;
    if (!smem_set) {
        cudaFuncSetAttribute(gemm_mma_kernel,
                             cudaFuncAttributeMaxDynamicSharedMemorySize, GEMM_SMEM);
        smem_set = 1;
    }

    prep_w_kernel<<<CO * CK / 4 / 256, 256>>>(rw);
    conv_offmod_kernel<<<256, 128>>>(x, res, ow, mw);
    sample_kernel<<<dim3(HW / PTILE, BATCH), 256>>>(x, ob, mb);
    gemm_mma_kernel<<<dim3(HW / 128, CO / 128, BATCH), 256, GEMM_SMEM>>>(out);
}

// round 4
// speedup vs baseline: 2.7272x; 1.6386x over previous
#include <cuda_runtime.h>
#include <cuda_fp16.h>
#include <cstdint>
#include <math.h>

// Problem constants
#define BATCH 2
#define C 256
#define H 64
#define W 64
#define HW 4096
#define K2 9
#define CO 256
#define CK 2304        // C*K2
#define G 4            // channel groups for conv partial sums

// Scratch (__device__ globals; allocation-free rule)
__device__ float  g_part[BATCH * G * 27 * HW];     // [b][g][o(27)][p]
__device__ __half g_vh[(size_t)BATCH * HW * CK];   // [b][p][ck] K-major fp16
__device__ __half g_wh[(size_t)CO * CK];           // W fp16, K-major

// ---------------------------------------------------------------------------
// helpers
// ---------------------------------------------------------------------------
__device__ __forceinline__ uint32_t smem_u32(const void* p) {
    uint32_t a;
    asm("{ .reg .u64 t; cvta.to.shared.u64 t, %1; cvt.u32.u64 %0, t; }" : "=r"(a) : "l"(p));
    return a;
}
__device__ __forceinline__ void cp_async16(uint32_t dst, const void* src) {
    asm volatile("cp.async.cg.shared.global [%0], [%1], 16;" :: "r"(dst), "l"(src));
}
#define CP_COMMIT() asm volatile("cp.async.commit_group;" ::: "memory")
#define CP_WAIT(n)  asm volatile("cp.async.wait_group %0;" :: "n"(n) : "memory")
#define SWZ128(off) ((off) ^ (((off) >> 3) & 0x70))

#define LDSM4(r, addr) \
    asm volatile("ldmatrix.sync.aligned.m8n8.x4.shared.b16 {%0,%1,%2,%3}, [%4];" \
        : "=r"((r)[0]), "=r"((r)[1]), "=r"((r)[2]), "=r"((r)[3]) : "r"(addr))

__device__ __forceinline__ void mma16816(float c[4], const uint32_t a[4], const uint32_t b[2]) {
    asm volatile(
        "mma.sync.aligned.m16n8k16.row.col.f32.f16.f16.f32 "
        "{%0,%1,%2,%3}, {%4,%5,%6,%7}, {%8,%9}, {%0,%1,%2,%3};"
        : "+f"(c[0]), "+f"(c[1]), "+f"(c[2]), "+f"(c[3])
        : "r"(a[0]), "r"(a[1]), "r"(a[2]), "r"(a[3]), "r"(b[0]), "r"(b[1]));
}

// ---------------------------------------------------------------------------
// Kernel 0: convert reg_w to fp16 (K-major rows of o)
// ---------------------------------------------------------------------------
__global__ __launch_bounds__(256)
void prep_w_kernel(const float* __restrict__ w)
{
    const int i = blockIdx.x * 256 + threadIdx.x;   // CO*CK/4 = 147456
    const float4 v = ((const float4*)w)[i];
    __half2* dst = (__half2*)(g_wh + (size_t)i * 4);
    dst[0] = __floats2half2_rn(v.x, v.y);
    dst[1] = __floats2half2_rn(v.z, v.w);
}

// ---------------------------------------------------------------------------
// Kernel 1: offset conv (18ch from residual) + mod conv (9ch from x),
// partial over G=4 channel groups. 128-thread blocks, 256 blocks.
// ---------------------------------------------------------------------------
__global__ __launch_bounds__(128)
void conv_offmod_kernel(const float* __restrict__ x,
                        const float* __restrict__ res,
                        const float* __restrict__ ow,   // [18][C][9]
                        const float* __restrict__ mw)   // [9][C][9]
{
    __shared__ __align__(16) float sw[32 * 27 * 12];

    const int tid  = threadIdx.x;
    const int bidx = blockIdx.x;          // B*G*32 = 256 blocks
    const int pblk = bidx & 31;
    const int g    = (bidx >> 5) & (G - 1);
    const int b    = bidx >> 7;
    const int p    = pblk * 128 + tid;
    const int h    = p >> 6;
    const int w    = p & 63;

    float acc[27];
#pragma unroll
    for (int o = 0; o < 27; ++o) acc[o] = 0.f;

    const float* xb = x   + (size_t)b * C * HW;
    const float* rb = res + (size_t)b * C * HW;

    for (int cc = 0; cc < 2; ++cc) {
        const int cbase = g * 64 + cc * 32;

        __syncthreads();
        for (int i = tid; i < 32 * 243; i += 128) {
            const int ci = i / 243;
            const int t  = i % 243;
            const int c  = cbase + ci;
            const int o  = t / 9;
            const int tt = t % 9;
            float wv;
            if (o < 18) wv = ow[(size_t)o * CK + c * 9 + tt];
            else        wv = mw[(size_t)(o - 18) * CK + c * 9 + tt];
            sw[ci * 324 + o * 12 + tt] = wv;
        }
        __syncthreads();

        for (int ci = 0; ci < 32; ++ci) {
            const int c = cbase + ci;
            const float* xc = xb + (size_t)c * HW;
            const float* rc = rb + (size_t)c * HW;

            float rv[9], xv[9];
#pragma unroll
            for (int r = 0; r < 3; ++r) {
                const int hh = h + r - 1;
                const bool vy = ((unsigned)hh < 64u);
#pragma unroll
                for (int s = 0; s < 3; ++s) {
                    const int ww = w + s - 1;
                    const bool v = vy && ((unsigned)ww < 64u);
                    const int idx = hh * 64 + ww;
                    rv[r * 3 + s] = v ? rc[idx] : 0.f;
                    xv[r * 3 + s] = v ? xc[idx] : 0.f;
                }
            }

            const float* swc = sw + ci * 324;
#pragma unroll
            for (int o = 0; o < 18; ++o) {
                const float4 wA = *(const float4*)(swc + o * 12);
                const float4 wB = *(const float4*)(swc + o * 12 + 4);
                const float  wC = swc[o * 12 + 8];
                acc[o] += wA.x * rv[0] + wA.y * rv[1] + wA.z * rv[2] + wA.w * rv[3]
                        + wB.x * rv[4] + wB.y * rv[5] + wB.z * rv[6] + wB.w * rv[7]
                        + wC  * rv[8];
            }
#pragma unroll
            for (int o = 0; o < 9; ++o) {
                const float4 wA = *(const float4*)(swc + (18 + o) * 12);
                const float4 wB = *(const float4*)(swc + (18 + o) * 12 + 4);
                const float  wC = swc[(18 + o) * 12 + 8];
                acc[18 + o] += wA.x * xv[0] + wA.y * xv[1] + wA.z * xv[2] + wA.w * xv[3]
                             + wB.x * xv[4] + wB.y * xv[5] + wB.z * xv[6] + wB.w * xv[7]
                             + wC  * xv[8];
            }
        }
    }

    float* outp = g_part + (size_t)(b * G + g) * 27 * HW;
#pragma unroll
    for (int o = 0; o < 27; ++o) outp[o * HW + p] = acc[o];
}

// ---------------------------------------------------------------------------
// Kernel 2: sampling. Block = 288 threads (warp = tap k, lane = pixel p).
// All bilinear indices/weights live in registers. Gathers loop over channels;
// smem transpose -> coalesced fp16 write of g_vh[b][p][ck].
// ---------------------------------------------------------------------------
#define SVPAD 293   // gcd(293%32=5,32)=1 -> conflict-free scattered stores
__global__ __launch_bounds__(288)
void sample_kernel(const float* __restrict__ x,
                   const float* __restrict__ ob,   // [18]
                   const float* __restrict__ mb)   // [9]
{
    __shared__ float sv[32 * SVPAD];

    const int tid  = threadIdx.x;
    const int lane = tid & 31;
    const int k    = tid >> 5;           // 0..8
    const int b    = blockIdx.y;
    const int p0   = blockIdx.x * 32;
    const int p    = p0 + lane;
    const int h    = p >> 6;
    const int w    = p & 63;

    // --- per-thread offsets/weights (registers only) ---
    const float* pb = g_part + (size_t)b * G * 27 * HW;
    float dy   = ob[2 * k];
    float dx   = ob[2 * k + 1];
    float mraw = mb[k];
#pragma unroll
    for (int g = 0; g < G; ++g) {
        dy   += pb[(g * 27 + 2 * k)     * HW + p];
        dx   += pb[(g * 27 + 2 * k + 1) * HW + p];
        mraw += pb[(g * 27 + 18 + k)    * HW + p];
    }
    const float m = 2.f / (1.f + expf(-mraw));

    const float py = dy + (float)(h - 1 + k / 3);
    const float px = dx + (float)(w - 1 + k % 3);
    const float y0f = floorf(py), x0f = floorf(px);
    const float wy1 = py - y0f,  wx1 = px - x0f;
    const float wy0 = 1.f - wy1, wx0 = 1.f - wx1;
    const int y0 = (int)y0f, x0 = (int)x0f;
    const int y1 = y0 + 1,   x1 = x0 + 1;

    int   l00, l01, l10, l11;
    float w00, w01, w10, w11;
    {
        bool v; int yc, xc;
        v = ((unsigned)y0 < 64u) && ((unsigned)x0 < 64u);
        yc = min(max(y0, 0), 63); xc = min(max(x0, 0), 63);
        l00 = yc * 64 + xc; w00 = v ? wy0 * wx0 * m : 0.f;
        v = ((unsigned)y0 < 64u) && ((unsigned)x1 < 64u);
        yc = min(max(y0, 0), 63); xc = min(max(x1, 0), 63);
        l01 = yc * 64 + xc; w01 = v ? wy0 * wx1 * m : 0.f;
        v = ((unsigned)y1 < 64u) && ((unsigned)x0 < 64u);
        yc = min(max(y1, 0), 63); xc = min(max(x0, 0), 63);
        l10 = yc * 64 + xc; w10 = v ? wy1 * wx0 * m : 0.f;
        v = ((unsigned)y1 < 64u) && ((unsigned)x1 < 64u);
        yc = min(max(y1, 0), 63); xc = min(max(x1, 0), 63);
        l11 = yc * 64 + xc; w11 = v ? wy1 * wx1 * m : 0.f;
    }

    const float* xb = x + (size_t)b * C * HW;
    float* svp = sv + lane * SVPAD + k;

    for (int c0 = 0; c0 < C; c0 += 32) {
        const float* xc = xb + (size_t)c0 * HW;
#pragma unroll 4
        for (int ci = 0; ci < 32; ++ci) {
            const float val = w00 * __ldg(xc + l00) + w01 * __ldg(xc + l01)
                            + w10 * __ldg(xc + l10) + w11 * __ldg(xc + l11);
            svp[ci * 9] = val;
            xc += HW;
        }
        __syncthreads();

        __half* dst = g_vh + ((size_t)(b * HW + p0)) * CK + c0 * 9;
#pragma unroll 4
        for (int pass = 0; pass < 32; ++pass)
            dst[(size_t)pass * CK + tid] = __float2half_rn(sv[pass * SVPAD + tid]);
        __syncthreads();
    }
}

// ---------------------------------------------------------------------------
// Kernel 3: fp16 mma.sync GEMM with ldmatrix + SW128 swizzle.
//   out[b][o][p] = sum_ck W[o][ck] * V[b][p][ck]
// Block tile 128(o) x 128(p), BK=64 halves (128B rows), 3-stage cp.async.
// 8 warps, each 64x32 via m16n8k16.
// ---------------------------------------------------------------------------
#define BKH   64
#define TILEB 16384                     // 128 rows * 128 B
#define STAGEB (2 * TILEB)
#define NSTAGE 3
#define NCH   (CK / BKH)                // 36
#define GEMM_SMEM (NSTAGE * STAGEB)     // 98304

__global__ __launch_bounds__(256)
void gemm_mma_kernel(float* __restrict__ out)
{
    extern __shared__ char smc[];
    const uint32_t sb = smem_u32(smc);

    const int tid  = threadIdx.x;
    const int lane = tid & 31;
    const int wid  = tid >> 5;
    const int b    = blockIdx.z;
    const int m0   = blockIdx.y * 128;   // o
    const int n0   = blockIdx.x * 128;   // p

    const __half* gA = g_wh + (size_t)m0 * CK;
    const __half* gB = g_vh + ((size_t)(b * HW + n0)) * CK;

    // loader: row = tid>>1, half-row of 32 halves (64B) per thread
    const int lr  = tid >> 1;
    const int seg = tid & 1;
    const __half* pa = gA + (size_t)lr * CK + seg * 32;
    const __half* pv = gB + (size_t)lr * CK + seg * 32;
    uint32_t swo[4];
#pragma unroll
    for (int j = 0; j < 4; ++j)
        swo[j] = SWZ128((uint32_t)(lr * 128 + seg * 64 + j * 16));

#define LOAD_TILE(stage, ch) do {                                             \
        const uint32_t _s = sb + (stage) * STAGEB;                            \
        const __half* _pa = pa + (size_t)(ch) * BKH;                          \
        const __half* _pv = pv + (size_t)(ch) * BKH;                          \
        cp_async16(_s + swo[0],         _pa);                                 \
        cp_async16(_s + swo[1],         _pa + 8);                             \
        cp_async16(_s + swo[2],         _pa + 16);                            \
        cp_async16(_s + swo[3],         _pa + 24);                            \
        cp_async16(_s + TILEB + swo[0], _pv);                                 \
        cp_async16(_s + TILEB + swo[1], _pv + 8);                             \
        cp_async16(_s + TILEB + swo[2], _pv + 16);                            \
        cp_async16(_s + TILEB + swo[3], _pv + 24);                            \
    } while (0)

    // ldmatrix fragment base offsets (stage 0, k-step 0)
    const int wm = (wid >> 2) * 64;     // warp m (o)
    const int wn = (wid & 3) * 32;      // warp n (p)
    uint32_t aOff[4], bOff[2];
#pragma unroll
    for (int mt = 0; mt < 4; ++mt) {
        const uint32_t off = (uint32_t)((wm + mt * 16 + (lane & 15)) * 128
                                        + ((lane & 16) ? 16 : 0));
        aOff[mt] = SWZ128(off);
    }
#pragma unroll
    for (int ntp = 0; ntp < 2; ++ntp) {
        const uint32_t off = (uint32_t)((wn + ntp * 16 + ((lane & 16) ? 8 : 0) + (lane & 7)) * 128
                                        + ((lane & 8) ? 16 : 0));
        bOff[ntp] = TILEB + SWZ128(off);
    }

    float c[16][4];
#pragma unroll
    for (int i = 0; i < 16; ++i)
#pragma unroll
        for (int j = 0; j < 4; ++j) c[i][j] = 0.f;

    LOAD_TILE(0, 0); CP_COMMIT();
    LOAD_TILE(1, 1); CP_COMMIT();

    int stage = 0;
    for (int ch = 0; ch < NCH; ++ch) {
        if (ch + 2 < NCH) {
            const int ns = (stage + 2 >= NSTAGE) ? stage + 2 - NSTAGE : stage + 2;
            LOAD_TILE(ns, ch + 2);
        }
        CP_COMMIT();
        CP_WAIT(2);
        __syncthreads();

        const uint32_t sbase = sb + stage * STAGEB;
#pragma unroll
        for (int s = 0; s < 4; ++s) {
            uint32_t a[4][4], bb[2][4];
#pragma unroll
            for (int mt = 0; mt < 4; ++mt)
                LDSM4(a[mt], sbase + (aOff[mt] ^ (s << 5)));
#pragma unroll
            for (int ntp = 0; ntp < 2; ++ntp)
                LDSM4(bb[ntp], sbase + (bOff[ntp] ^ (s << 5)));
#pragma unroll
            for (int mt = 0; mt < 4; ++mt)
#pragma unroll
                for (int nt = 0; nt < 4; ++nt)
                    mma16816(c[mt * 4 + nt], a[mt], &bb[nt >> 1][(nt & 1) * 2]);
        }
        __syncthreads();
        stage = (stage + 1 >= NSTAGE) ? 0 : stage + 1;
    }

    // epilogue: frag (m16n8): c0,c1 -> row qr, cols 2qc,2qc+1 ; c2,c3 -> row qr+8
    const int qr = lane >> 2;
    const int qc = lane & 3;
#pragma unroll
    for (int mt = 0; mt < 4; ++mt) {
#pragma unroll
        for (int nt = 0; nt < 4; ++nt) {
            const int o = m0 + wm + mt * 16 + qr;
            const int p = n0 + wn + nt * 8 + 2 * qc;
            float* o0 = out + ((size_t)(b * CO + o)) * HW + p;
            float2 v0; v0.x = c[mt * 4 + nt][0]; v0.y = c[mt * 4 + nt][1];
            *(float2*)o0 = v0;
            float2 v1; v1.x = c[mt * 4 + nt][2]; v1.y = c[mt * 4 + nt][3];
            *(float2*)(o0 + 8 * HW) = v1;
        }
    }
}

// ---------------------------------------------------------------------------
extern "C" void kernel_launch(void* const* d_in, const int* in_sizes, int n_in,
                              void* d_out, int out_size)
{
    const float* x   = (const float*)d_in[0];   // [2,256,64,64]
    const float* res = (const float*)d_in[1];   // [2,256,64,64]
    const float* ow  = (const float*)d_in[2];   // [18,256,3,3]
    const float* ob  = (const float*)d_in[3];   // [18]
    const float* mw  = (const float*)d_in[4];   // [9,256,3,3]
    const float* mb  = (const float*)d_in[5];   // [9]
    const float* rw  = (const float*)d_in[6];   // [256,256,3,3]
    float* out = (float*)d_out;                 // [2,256,64,64]

    static int smem_set = 0;
    if (!smem_set) {
        cudaFuncSetAttribute(gemm_mma_kernel,
                             cudaFuncAttributeMaxDynamicSharedMemorySize, GEMM_SMEM);
        smem_set = 1;
    }

    prep_w_kernel<<<CO * CK / 4 / 256, 256>>>(rw);
    conv_offmod_kernel<<<256, 128>>>(x, res, ow, mw);
    sample_kernel<<<dim3(HW / 32, BATCH), 288>>>(x, ob, mb);
    gemm_mma_kernel<<<dim3(HW / 128, CO / 128, BATCH), 256, GEMM_SMEM>>>(out);
}

// round 5
// speedup vs baseline: 3.0411x; 1.1151x over previous
#include <cuda_runtime.h>
#include <cuda_fp16.h>
#include <cstdint>
#include <math.h>

// Problem constants
#define BATCH 2
#define C 256
#define H 64
#define W 64
#define HW 4096
#define K2 9
#define CO 256
#define CK 2304        // C*K2
#define G 8            // channel groups for conv partial sums (32 ch each)

// Scratch (__device__ globals; allocation-free rule)
__device__ float  g_part[BATCH * G * 27 * HW];     // [b][g][o(27)][p]
__device__ __half g_vh[(size_t)BATCH * CK * HW];   // [b][ck][p]  p-contiguous fp16
__device__ __half g_wh[(size_t)CO * CK];           // W fp16, K-major rows of o

// ---------------------------------------------------------------------------
// helpers
// ---------------------------------------------------------------------------
__device__ __forceinline__ uint32_t smem_u32(const void* p) {
    uint32_t a;
    asm("{ .reg .u64 t; cvta.to.shared.u64 t, %1; cvt.u32.u64 %0, t; }" : "=r"(a) : "l"(p));
    return a;
}
__device__ __forceinline__ void cp_async16(uint32_t dst, const void* src) {
    asm volatile("cp.async.cg.shared.global [%0], [%1], 16;" :: "r"(dst), "l"(src));
}
#define CP_COMMIT() asm volatile("cp.async.commit_group;" ::: "memory")
#define CP_WAIT(n)  asm volatile("cp.async.wait_group %0;" :: "n"(n) : "memory")
#define SWZ128(off) ((off) ^ (((off) >> 3) & 0x70))

#define LDSM4(r, addr) \
    asm volatile("ldmatrix.sync.aligned.m8n8.x4.shared.b16 {%0,%1,%2,%3}, [%4];" \
        : "=r"((r)[0]), "=r"((r)[1]), "=r"((r)[2]), "=r"((r)[3]) : "r"(addr))
#define LDSM4T(r, addr) \
    asm volatile("ldmatrix.sync.aligned.m8n8.x4.trans.shared.b16 {%0,%1,%2,%3}, [%4];" \
        : "=r"((r)[0]), "=r"((r)[1]), "=r"((r)[2]), "=r"((r)[3]) : "r"(addr))

__device__ __forceinline__ void mma16816(float c[4], const uint32_t a[4], const uint32_t b[2]) {
    asm volatile(
        "mma.sync.aligned.m16n8k16.row.col.f32.f16.f16.f32 "
        "{%0,%1,%2,%3}, {%4,%5,%6,%7}, {%8,%9}, {%0,%1,%2,%3};"
        : "+f"(c[0]), "+f"(c[1]), "+f"(c[2]), "+f"(c[3])
        : "r"(a[0]), "r"(a[1]), "r"(a[2]), "r"(a[3]), "r"(b[0]), "r"(b[1]));
}

// ---------------------------------------------------------------------------
// Kernel 0: convert reg_w to fp16 (K-major rows of o)
// ---------------------------------------------------------------------------
__global__ __launch_bounds__(256)
void prep_w_kernel(const float* __restrict__ w)
{
    const int i = blockIdx.x * 256 + threadIdx.x;   // CO*CK/4 = 147456
    const float4 v = ((const float4*)w)[i];
    __half2* dst = (__half2*)(g_wh + (size_t)i * 4);
    dst[0] = __floats2half2_rn(v.x, v.y);
    dst[1] = __floats2half2_rn(v.z, v.w);
}

// ---------------------------------------------------------------------------
// Kernel 1: offset conv (18ch from residual) + mod conv (9ch from x).
// 2 pixels/thread, G=8 channel groups (32 ch each), 256 blocks x 128 thr.
// ---------------------------------------------------------------------------
__global__ __launch_bounds__(128)
void conv_offmod_kernel(const float* __restrict__ x,
                        const float* __restrict__ res,
                        const float* __restrict__ ow,   // [18][C][9]
                        const float* __restrict__ mw)   // [9][C][9]
{
    __shared__ __align__(16) float sw[32 * 27 * 12];    // 41.5 KB

    const int tid  = threadIdx.x;
    const int bidx = blockIdx.x;          // B*G*16 = 256 blocks
    const int pblk = bidx & 15;
    const int g    = (bidx >> 4) & (G - 1);
    const int b    = bidx >> 7;
    const int p    = pblk * 256 + tid * 2;    // even; pair (p, p+1) same row
    const int h    = p >> 6;
    const int w    = p & 63;

    float acc0[27], acc1[27];
#pragma unroll
    for (int o = 0; o < 27; ++o) { acc0[o] = 0.f; acc1[o] = 0.f; }

    const int cbase = g * 32;
    // stage weights for this group's 32 channels
    for (int i = tid; i < 32 * 243; i += 128) {
        const int ci = i / 243;
        const int t  = i % 243;
        const int c  = cbase + ci;
        const int o  = t / 9;
        const int tt = t % 9;
        float wv;
        if (o < 18) wv = ow[(size_t)o * CK + c * 9 + tt];
        else        wv = mw[(size_t)(o - 18) * CK + c * 9 + tt];
        sw[ci * 324 + o * 12 + tt] = wv;
    }
    __syncthreads();

    const float* xb = x   + (size_t)b * C * HW;
    const float* rb = res + (size_t)b * C * HW;

    for (int ci = 0; ci < 32; ++ci) {
        const int c = cbase + ci;
        const float* xc = xb + (size_t)c * HW;
        const float* rc = rb + (size_t)c * HW;

        // patch rows 3 x cols 4 covering both pixels
        float rv[12], xv[12];
#pragma unroll
        for (int r = 0; r < 3; ++r) {
            const int hh = h + r - 1;
            const bool vy = ((unsigned)hh < 64u);
#pragma unroll
            for (int s = 0; s < 4; ++s) {
                const int ww = w + s - 1;
                const bool v = vy && ((unsigned)ww < 64u);
                const int idx = hh * 64 + ww;
                rv[r * 4 + s] = v ? rc[idx] : 0.f;
                xv[r * 4 + s] = v ? xc[idx] : 0.f;
            }
        }

        const float* swc = sw + ci * 324;
#pragma unroll
        for (int o = 0; o < 18; ++o) {
            const float4 wA = *(const float4*)(swc + o * 12);
            const float4 wB = *(const float4*)(swc + o * 12 + 4);
            const float  wC = swc[o * 12 + 8];
            acc0[o] += wA.x * rv[0] + wA.y * rv[1] + wA.z * rv[2]
                     + wA.w * rv[4] + wB.x * rv[5] + wB.y * rv[6]
                     + wB.z * rv[8] + wB.w * rv[9] + wC * rv[10];
            acc1[o] += wA.x * rv[1] + wA.y * rv[2] + wA.z * rv[3]
                     + wA.w * rv[5] + wB.x * rv[6] + wB.y * rv[7]
                     + wB.z * rv[9] + wB.w * rv[10] + wC * rv[11];
        }
#pragma unroll
        for (int o = 0; o < 9; ++o) {
            const float4 wA = *(const float4*)(swc + (18 + o) * 12);
            const float4 wB = *(const float4*)(swc + (18 + o) * 12 + 4);
            const float  wC = swc[(18 + o) * 12 + 8];
            acc0[18 + o] += wA.x * xv[0] + wA.y * xv[1] + wA.z * xv[2]
                          + wA.w * xv[4] + wB.x * xv[5] + wB.y * xv[6]
                          + wB.z * xv[8] + wB.w * xv[9] + wC * xv[10];
            acc1[18 + o] += wA.x * xv[1] + wA.y * xv[2] + wA.z * xv[3]
                          + wA.w * xv[5] + wB.x * xv[6] + wB.y * xv[7]
                          + wB.z * xv[9] + wB.w * xv[10] + wC * xv[11];
        }
    }

    float* outp = g_part + (size_t)(b * G + g) * 27 * HW;
#pragma unroll
    for (int o = 0; o < 27; ++o) {
        float2 v; v.x = acc0[o]; v.y = acc1[o];
        *(float2*)(outp + o * HW + p) = v;
    }
}

// ---------------------------------------------------------------------------
// Kernel 2: sampling. 288 threads: warp = tap k, lane = pixel p.
// Registers-only bilinear setup; writes g_vh[b][ck][p] directly (64B/warp,
// coalesced). No smem, no syncs.
// ---------------------------------------------------------------------------
__global__ __launch_bounds__(288)
void sample_kernel(const float* __restrict__ x,
                   const float* __restrict__ ob,   // [18]
                   const float* __restrict__ mb)   // [9]
{
    const int tid  = threadIdx.x;
    const int lane = tid & 31;
    const int k    = tid >> 5;           // 0..8
    const int b    = blockIdx.y;
    const int p0   = blockIdx.x * 32;
    const int p    = p0 + lane;
    const int h    = p >> 6;
    const int w    = p & 63;

    const float* pb = g_part + (size_t)b * G * 27 * HW;
    float dy   = ob[2 * k];
    float dx   = ob[2 * k + 1];
    float mraw = mb[k];
#pragma unroll
    for (int g = 0; g < G; ++g) {
        dy   += pb[(g * 27 + 2 * k)     * HW + p];
        dx   += pb[(g * 27 + 2 * k + 1) * HW + p];
        mraw += pb[(g * 27 + 18 + k)    * HW + p];
    }
    const float m = 2.f / (1.f + expf(-mraw));

    const float py = dy + (float)(h - 1 + k / 3);
    const float px = dx + (float)(w - 1 + k % 3);
    const float y0f = floorf(py), x0f = floorf(px);
    const float wy1 = py - y0f,  wx1 = px - x0f;
    const float wy0 = 1.f - wy1, wx0 = 1.f - wx1;
    const int y0 = (int)y0f, x0 = (int)x0f;
    const int y1 = y0 + 1,   x1 = x0 + 1;

    int   l00, l01, l10, l11;
    float w00, w01, w10, w11;
    {
        bool v; int yc, xc;
        v = ((unsigned)y0 < 64u) && ((unsigned)x0 < 64u);
        yc = min(max(y0, 0), 63); xc = min(max(x0, 0), 63);
        l00 = yc * 64 + xc; w00 = v ? wy0 * wx0 * m : 0.f;
        v = ((unsigned)y0 < 64u) && ((unsigned)x1 < 64u);
        yc = min(max(y0, 0), 63); xc = min(max(x1, 0), 63);
        l01 = yc * 64 + xc; w01 = v ? wy0 * wx1 * m : 0.f;
        v = ((unsigned)y1 < 64u) && ((unsigned)x0 < 64u);
        yc = min(max(y1, 0), 63); xc = min(max(x0, 0), 63);
        l10 = yc * 64 + xc; w10 = v ? wy1 * wx0 * m : 0.f;
        v = ((unsigned)y1 < 64u) && ((unsigned)x1 < 64u);
        yc = min(max(y1, 0), 63); xc = min(max(x1, 0), 63);
        l11 = yc * 64 + xc; w11 = v ? wy1 * wx1 * m : 0.f;
    }

    const float* xc = x + (size_t)b * C * HW;
    __half* dst = g_vh + ((size_t)b * CK + k) * HW + p;

#pragma unroll 4
    for (int c = 0; c < C; ++c) {
        const float val = w00 * __ldg(xc + l00) + w01 * __ldg(xc + l01)
                        + w10 * __ldg(xc + l10) + w11 * __ldg(xc + l11);
        *dst = __float2half_rn(val);
        xc  += HW;
        dst += (size_t)9 * HW;
    }
}

// ---------------------------------------------------------------------------
// Kernel 3: fp16 mma.sync GEMM, tile 64(o) x 128(p), BK=64, 3-stage cp.async.
//   out[b][o][p] = sum_ck W[o][ck] * V[b][ck][p]
// A = g_wh (row-major MxK, 128B rows, SW128 + ldmatrix).
// B = g_vh (row-major KxN, 256B rows, XOR-swizzled 16B cols + ldmatrix.trans).
// 8 warps: 2(m) x 4(n), each 32x32. Grid 256 blocks, 2 blocks/SM.
// ---------------------------------------------------------------------------
#define BKH    64
#define ATILEB 8192                      // 64 rows * 128 B
#define BTILEB 16384                     // 64 k-rows * 256 B
#define STAGEB (ATILEB + BTILEB)         // 24 KB
#define NSTAGE 3
#define NCH    (CK / BKH)                // 36
#define GEMM_SMEM (NSTAGE * STAGEB)      // 73728 B

__global__ __launch_bounds__(256)
void gemm_mma_kernel(float* __restrict__ out)
{
    extern __shared__ char smc[];
    const uint32_t sb = smem_u32(smc);

    const int tid  = threadIdx.x;
    const int lane = tid & 31;
    const int wid  = tid >> 5;
    const int b    = blockIdx.z;
    const int m0   = blockIdx.y * 64;    // o
    const int n0   = blockIdx.x * 128;   // p

    const __half* gA = g_wh + (size_t)m0 * CK;
    const __half* gB = g_vh + (size_t)b * CK * HW + n0;

    // ---- A loader (threads 0..127): row = t>>1, 64B half-row, SW128 ----
    const int ar  = tid >> 1;            // 0..127 (used if <128 -> rows 0..63)
    const int seg = tid & 1;
    const __half* pa = gA + (size_t)(ar) * CK + seg * 32;
    uint32_t aswo[4];
#pragma unroll
    for (int j = 0; j < 4; ++j)
        aswo[j] = SWZ128((uint32_t)(ar * 128 + seg * 64 + j * 16));

    // ---- B loader (all 256 threads): k-row = t>>2, 4x16B cols ----
    const int br = tid >> 2;             // 0..63
    const int cg = tid & 3;
    const __half* pv = gB + (size_t)br * HW + cg * 32;
    uint32_t bswo[4];
#pragma unroll
    for (int j = 0; j < 4; ++j) {
        const int cc = cg * 4 + j;       // 16B col 0..15
        bswo[j] = ATILEB + (uint32_t)br * 256 + ((uint32_t)(cc ^ (br & 7)) << 4);
    }

#define LOAD_TILE(stage, ch) do {                                             \
        const uint32_t _s = sb + (stage) * STAGEB;                            \
        if (tid < 128) {                                                      \
            const __half* _pa = pa + (size_t)(ch) * BKH;                      \
            cp_async16(_s + aswo[0], _pa);                                    \
            cp_async16(_s + aswo[1], _pa + 8);                                \
            cp_async16(_s + aswo[2], _pa + 16);                               \
            cp_async16(_s + aswo[3], _pa + 24);                               \
        }                                                                     \
        const __half* _pv = pv + (size_t)(ch) * BKH * HW;                     \
        cp_async16(_s + bswo[0], _pv);                                        \
        cp_async16(_s + bswo[1], _pv + 8);                                    \
        cp_async16(_s + bswo[2], _pv + 16);                                   \
        cp_async16(_s + bswo[3], _pv + 24);                                   \
    } while (0)

    // ---- ldmatrix offsets ----
    const int wm = (wid >> 2) * 32;      // warp m (o): 0 / 32
    const int wn = (wid & 3) * 32;       // warp n (p): 0..96
    uint32_t aOff[2];
#pragma unroll
    for (int mt = 0; mt < 2; ++mt) {
        const uint32_t off = (uint32_t)((wm + mt * 16 + (lane & 15)) * 128
                                        + ((lane & 16) ? 16 : 0));
        aOff[mt] = SWZ128(off);
    }
    // B trans: matrix idx mIdx = lane>>3; k_off = (mIdx&1)*8 + (lane&7);
    //          16B col = wn/8 + (mIdx>>1)  (+2 for the second x4)
    const int mIdx = lane >> 3;
    const int koff = ((mIdx & 1) << 3) + (lane & 7);
    const int cc0  = (wn >> 3) + (mIdx >> 1);
    const int cc1  = cc0 + 2;
    const uint32_t bO0 = ATILEB + (uint32_t)koff * 256 + ((uint32_t)(cc0 ^ (koff & 7)) << 4);
    const uint32_t bO1 = ATILEB + (uint32_t)koff * 256 + ((uint32_t)(cc1 ^ (koff & 7)) << 4);

    float c[8][4];
#pragma unroll
    for (int i = 0; i < 8; ++i)
#pragma unroll
        for (int j = 0; j < 4; ++j) c[i][j] = 0.f;

    LOAD_TILE(0, 0); CP_COMMIT();
    LOAD_TILE(1, 1); CP_COMMIT();

    int stage = 0;
    for (int ch = 0; ch < NCH; ++ch) {
        if (ch + 2 < NCH) {
            const int ns = (stage + 2 >= NSTAGE) ? stage + 2 - NSTAGE : stage + 2;
            LOAD_TILE(ns, ch + 2);
        }
        CP_COMMIT();
        CP_WAIT(2);
        __syncthreads();

        const uint32_t sbase = sb + stage * STAGEB;
#pragma unroll
        for (int s = 0; s < 4; ++s) {           // k16 steps within BK=64
            uint32_t a[2][4], b0[4], b1[4];
#pragma unroll
            for (int mt = 0; mt < 2; ++mt)
                LDSM4(a[mt], sbase + (aOff[mt] ^ (s << 5)));
            LDSM4T(b0, sbase + bO0 + s * 4096);  // s*16 k-rows * 256B
            LDSM4T(b1, sbase + bO1 + s * 4096);
#pragma unroll
            for (int mt = 0; mt < 2; ++mt) {
                mma16816(c[mt * 4 + 0], a[mt], &b0[0]);
                mma16816(c[mt * 4 + 1], a[mt], &b0[2]);
                mma16816(c[mt * 4 + 2], a[mt], &b1[0]);
                mma16816(c[mt * 4 + 3], a[mt], &b1[2]);
            }
        }
        __syncthreads();
        stage = (stage + 1 >= NSTAGE) ? 0 : stage + 1;
    }

    // epilogue
    const int qr = lane >> 2;
    const int qc = lane & 3;
#pragma unroll
    for (int mt = 0; mt < 2; ++mt) {
#pragma unroll
        for (int nt = 0; nt < 4; ++nt) {
            const int o = m0 + wm + mt * 16 + qr;
            const int p = n0 + wn + nt * 8 + 2 * qc;
            float* o0 = out + ((size_t)(b * CO + o)) * HW + p;
            float2 v0; v0.x = c[mt * 4 + nt][0]; v0.y = c[mt * 4 + nt][1];
            *(float2*)o0 = v0;
            float2 v1; v1.x = c[mt * 4 + nt][2]; v1.y = c[mt * 4 + nt][3];
            *(float2*)(o0 + 8 * HW) = v1;
        }
    }
}

// ---------------------------------------------------------------------------
extern "C" void kernel_launch(void* const* d_in, const int* in_sizes, int n_in,
                              void* d_out, int out_size)
{
    const float* x   = (const float*)d_in[0];   // [2,256,64,64]
    const float* res = (const float*)d_in[1];   // [2,256,64,64]
    const float* ow  = (const float*)d_in[2];   // [18,256,3,3]
    const float* ob  = (const float*)d_in[3];   // [18]
    const float* mw  = (const float*)d_in[4];   // [9,256,3,3]
    const float* mb  = (const float*)d_in[5];   // [9]
    const float* rw  = (const float*)d_in[6];   // [256,256,3,3]
    float* out = (float*)d_out;                 // [2,256,64,64]

    static int smem_set = 0;
    if (!smem_set) {
        cudaFuncSetAttribute(gemm_mma_kernel,
                             cudaFuncAttributeMaxDynamicSharedMemorySize, GEMM_SMEM);
        smem_set = 1;
    }

    prep_w_kernel<<<CO * CK / 4 / 256, 256>>>(rw);
    conv_offmod_kernel<<<256, 128>>>(x, res, ow, mw);
    sample_kernel<<<dim3(HW / 32, BATCH), 288>>>(x, ob, mb);
    gemm_mma_kernel<<<dim3(HW / 128, CO / 64, BATCH), 256, GEMM_SMEM>>>(out);
}

// round 6
// speedup vs baseline: 3.1732x; 1.0435x over previous
#include <cuda_runtime.h>
#include <cuda_fp16.h>
#include <cstdint>
#include <math.h>

// Problem constants
#define BATCH 2
#define C 256
#define H 64
#define W 64
#define HW 4096
#define K2 9
#define CO 256
#define CK 2304        // C*K2
#define G 8            // channel groups for conv partial sums (32 ch each)

// Scratch (__device__ globals; allocation-free rule)
__device__ float  g_part[BATCH * G * 27 * HW];     // [b][g][o(27)][p]
__device__ __half g_vh[(size_t)BATCH * CK * HW];   // [b][ck][p]  p-contiguous fp16
__device__ __half g_wh[(size_t)CO * CK];           // W fp16, K-major rows of o

// ---------------------------------------------------------------------------
// helpers
// ---------------------------------------------------------------------------
__device__ __forceinline__ uint32_t smem_u32(const void* p) {
    uint32_t a;
    asm("{ .reg .u64 t; cvta.to.shared.u64 t, %1; cvt.u32.u64 %0, t; }" : "=r"(a) : "l"(p));
    return a;
}
__device__ __forceinline__ void cp_async16(uint32_t dst, const void* src) {
    asm volatile("cp.async.cg.shared.global [%0], [%1], 16;" :: "r"(dst), "l"(src));
}
#define CP_COMMIT() asm volatile("cp.async.commit_group;" ::: "memory")
#define CP_WAIT(n)  asm volatile("cp.async.wait_group %0;" :: "n"(n) : "memory")
#define SWZ128(off) ((off) ^ (((off) >> 3) & 0x70))

#define LDSM4(r, addr) \
    asm volatile("ldmatrix.sync.aligned.m8n8.x4.shared.b16 {%0,%1,%2,%3}, [%4];" \
        : "=r"((r)[0]), "=r"((r)[1]), "=r"((r)[2]), "=r"((r)[3]) : "r"(addr))
#define LDSM4T(r, addr) \
    asm volatile("ldmatrix.sync.aligned.m8n8.x4.trans.shared.b16 {%0,%1,%2,%3}, [%4];" \
        : "=r"((r)[0]), "=r"((r)[1]), "=r"((r)[2]), "=r"((r)[3]) : "r"(addr))

__device__ __forceinline__ void mma16816(float c[4], const uint32_t a[4], const uint32_t b[2]) {
    asm volatile(
        "mma.sync.aligned.m16n8k16.row.col.f32.f16.f16.f32 "
        "{%0,%1,%2,%3}, {%4,%5,%6,%7}, {%8,%9}, {%0,%1,%2,%3};"
        : "+f"(c[0]), "+f"(c[1]), "+f"(c[2]), "+f"(c[3])
        : "r"(a[0]), "r"(a[1]), "r"(a[2]), "r"(a[3]), "r"(b[0]), "r"(b[1]));
}

// ---------------------------------------------------------------------------
// Kernel 0: convert reg_w to fp16 (K-major rows of o)
// ---------------------------------------------------------------------------
__global__ __launch_bounds__(256)
void prep_w_kernel(const float* __restrict__ w)
{
    const int i = blockIdx.x * 256 + threadIdx.x;   // CO*CK/4 = 147456
    const float4 v = ((const float4*)w)[i];
    __half2* dst = (__half2*)(g_wh + (size_t)i * 4);
    dst[0] = __floats2half2_rn(v.x, v.y);
    dst[1] = __floats2half2_rn(v.z, v.w);
}

// ---------------------------------------------------------------------------
// Kernel 1: offset conv (18ch from residual) + mod conv (9ch from x).
// 2 pixels/thread, G=8 channel groups (32 ch each), 256 blocks x 128 thr.
// ---------------------------------------------------------------------------
__global__ __launch_bounds__(128)
void conv_offmod_kernel(const float* __restrict__ x,
                        const float* __restrict__ res,
                        const float* __restrict__ ow,   // [18][C][9]
                        const float* __restrict__ mw)   // [9][C][9]
{
    __shared__ __align__(16) float sw[32 * 27 * 12];    // 41.5 KB

    const int tid  = threadIdx.x;
    const int bidx = blockIdx.x;          // B*G*16 = 256 blocks
    const int pblk = bidx & 15;
    const int g    = (bidx >> 4) & (G - 1);
    const int b    = bidx >> 7;
    const int p    = pblk * 256 + tid * 2;    // even; pair (p, p+1) same row
    const int h    = p >> 6;
    const int w    = p & 63;

    float acc0[27], acc1[27];
#pragma unroll
    for (int o = 0; o < 27; ++o) { acc0[o] = 0.f; acc1[o] = 0.f; }

    const int cbase = g * 32;
    for (int i = tid; i < 32 * 243; i += 128) {
        const int ci = i / 243;
        const int t  = i % 243;
        const int c  = cbase + ci;
        const int o  = t / 9;
        const int tt = t % 9;
        float wv;
        if (o < 18) wv = ow[(size_t)o * CK + c * 9 + tt];
        else        wv = mw[(size_t)(o - 18) * CK + c * 9 + tt];
        sw[ci * 324 + o * 12 + tt] = wv;
    }
    __syncthreads();

    const float* xb = x   + (size_t)b * C * HW;
    const float* rb = res + (size_t)b * C * HW;

    for (int ci = 0; ci < 32; ++ci) {
        const int c = cbase + ci;
        const float* xc = xb + (size_t)c * HW;
        const float* rc = rb + (size_t)c * HW;

        float rv[12], xv[12];
#pragma unroll
        for (int r = 0; r < 3; ++r) {
            const int hh = h + r - 1;
            const bool vy = ((unsigned)hh < 64u);
#pragma unroll
            for (int s = 0; s < 4; ++s) {
                const int ww = w + s - 1;
                const bool v = vy && ((unsigned)ww < 64u);
                const int idx = hh * 64 + ww;
                rv[r * 4 + s] = v ? rc[idx] : 0.f;
                xv[r * 4 + s] = v ? xc[idx] : 0.f;
            }
        }

        const float* swc = sw + ci * 324;
#pragma unroll
        for (int o = 0; o < 18; ++o) {
            const float4 wA = *(const float4*)(swc + o * 12);
            const float4 wB = *(const float4*)(swc + o * 12 + 4);
            const float  wC = swc[o * 12 + 8];
            acc0[o] += wA.x * rv[0] + wA.y * rv[1] + wA.z * rv[2]
                     + wA.w * rv[4] + wB.x * rv[5] + wB.y * rv[6]
                     + wB.z * rv[8] + wB.w * rv[9] + wC * rv[10];
            acc1[o] += wA.x * rv[1] + wA.y * rv[2] + wA.z * rv[3]
                     + wA.w * rv[5] + wB.x * rv[6] + wB.y * rv[7]
                     + wB.z * rv[9] + wB.w * rv[10] + wC * rv[11];
        }
#pragma unroll
        for (int o = 0; o < 9; ++o) {
            const float4 wA = *(const float4*)(swc + (18 + o) * 12);
            const float4 wB = *(const float4*)(swc + (18 + o) * 12 + 4);
            const float  wC = swc[(18 + o) * 12 + 8];
            acc0[18 + o] += wA.x * xv[0] + wA.y * xv[1] + wA.z * xv[2]
                          + wA.w * xv[4] + wB.x * xv[5] + wB.y * xv[6]
                          + wB.z * xv[8] + wB.w * xv[9] + wC * xv[10];
            acc1[18 + o] += wA.x * xv[1] + wA.y * xv[2] + wA.z * xv[3]
                          + wA.w * xv[5] + wB.x * xv[6] + wB.y * xv[7]
                          + wB.z * xv[9] + wB.w * xv[10] + wC * xv[11];
        }
    }

    float* outp = g_part + (size_t)(b * G + g) * 27 * HW;
#pragma unroll
    for (int o = 0; o < 27; ++o) {
        float2 v; v.x = acc0[o]; v.y = acc1[o];
        *(float2*)(outp + o * HW + p) = v;
    }
}

// ---------------------------------------------------------------------------
// Kernel 2: sampling. 288 threads: warp = tap k, lane = pixel p.
// Registers-only bilinear setup; writes g_vh[b][ck][p] directly. Unroll 8
// for deep MLP over the 256-channel gather loop.
// ---------------------------------------------------------------------------
__global__ __launch_bounds__(288)
void sample_kernel(const float* __restrict__ x,
                   const float* __restrict__ ob,   // [18]
                   const float* __restrict__ mb)   // [9]
{
    const int tid  = threadIdx.x;
    const int lane = tid & 31;
    const int k    = tid >> 5;           // 0..8
    const int b    = blockIdx.y;
    const int p0   = blockIdx.x * 32;
    const int p    = p0 + lane;
    const int h    = p >> 6;
    const int w    = p & 63;

    const float* pb = g_part + (size_t)b * G * 27 * HW;
    float dy   = ob[2 * k];
    float dx   = ob[2 * k + 1];
    float mraw = mb[k];
#pragma unroll
    for (int g = 0; g < G; ++g) {
        dy   += pb[(g * 27 + 2 * k)     * HW + p];
        dx   += pb[(g * 27 + 2 * k + 1) * HW + p];
        mraw += pb[(g * 27 + 18 + k)    * HW + p];
    }
    const float m = 2.f / (1.f + expf(-mraw));

    const float py = dy + (float)(h - 1 + k / 3);
    const float px = dx + (float)(w - 1 + k % 3);
    const float y0f = floorf(py), x0f = floorf(px);
    const float wy1 = py - y0f,  wx1 = px - x0f;
    const float wy0 = 1.f - wy1, wx0 = 1.f - wx1;
    const int y0 = (int)y0f, x0 = (int)x0f;
    const int y1 = y0 + 1,   x1 = x0 + 1;

    int   l00, l01, l10, l11;
    float w00, w01, w10, w11;
    {
        bool v; int yc, xc;
        v = ((unsigned)y0 < 64u) && ((unsigned)x0 < 64u);
        yc = min(max(y0, 0), 63); xc = min(max(x0, 0), 63);
        l00 = yc * 64 + xc; w00 = v ? wy0 * wx0 * m : 0.f;
        v = ((unsigned)y0 < 64u) && ((unsigned)x1 < 64u);
        yc = min(max(y0, 0), 63); xc = min(max(x1, 0), 63);
        l01 = yc * 64 + xc; w01 = v ? wy0 * wx1 * m : 0.f;
        v = ((unsigned)y1 < 64u) && ((unsigned)x0 < 64u);
        yc = min(max(y1, 0), 63); xc = min(max(x0, 0), 63);
        l10 = yc * 64 + xc; w10 = v ? wy1 * wx0 * m : 0.f;
        v = ((unsigned)y1 < 64u) && ((unsigned)x1 < 64u);
        yc = min(max(y1, 0), 63); xc = min(max(x1, 0), 63);
        l11 = yc * 64 + xc; w11 = v ? wy1 * wx1 * m : 0.f;
    }

    const float* xc = x + (size_t)b * C * HW;
    __half* dst = g_vh + ((size_t)b * CK + k) * HW + p;

#pragma unroll 8
    for (int c = 0; c < C; ++c) {
        const float val = w00 * __ldg(xc + l00) + w01 * __ldg(xc + l01)
                        + w10 * __ldg(xc + l10) + w11 * __ldg(xc + l11);
        *dst = __float2half_rn(val);
        xc  += HW;
        dst += (size_t)9 * HW;
    }
}

// ---------------------------------------------------------------------------
// Kernel 3: fp16 mma.sync GEMM, tile 128(o) x 128(p), BK=64, 3-stage
// cp.async + register-fragment double buffering.
//   out[b][o][p] = sum_ck W[o][ck] * V[b][ck][p]
// A = g_wh (row-major MxK, 128B rows, SW128 + ldmatrix).
// B = g_vh (row-major KxN, 256B rows, XOR-swizzled 16B cols + ldmatrix.trans).
// 8 warps: 2(m) x 4(n), each 64x32.
// ---------------------------------------------------------------------------
#define BKH    64
#define ATILEB 16384                     // 128 rows * 128 B
#define BTILEB 16384                     // 64 k-rows * 256 B
#define STAGEB (ATILEB + BTILEB)         // 32 KB
#define NSTAGE 3
#define NCH    (CK / BKH)                // 36
#define GEMM_SMEM (NSTAGE * STAGEB)      // 98304 B

__global__ __launch_bounds__(256)
void gemm_mma_kernel(float* __restrict__ out)
{
    extern __shared__ char smc[];
    const uint32_t sb = smem_u32(smc);

    const int tid  = threadIdx.x;
    const int lane = tid & 31;
    const int wid  = tid >> 5;
    const int b    = blockIdx.z;
    const int m0   = blockIdx.y * 128;   // o
    const int n0   = blockIdx.x * 128;   // p

    const __half* gA = g_wh + (size_t)m0 * CK;
    const __half* gB = g_vh + (size_t)b * CK * HW + n0;

    // ---- A loader: row = t>>1 (0..127), 64B half-row, SW128 ----
    const int ar  = tid >> 1;
    const int seg = tid & 1;
    const __half* pa = gA + (size_t)ar * CK + seg * 32;
    uint32_t aswo[4];
#pragma unroll
    for (int j = 0; j < 4; ++j)
        aswo[j] = SWZ128((uint32_t)(ar * 128 + seg * 64 + j * 16));

    // ---- B loader: k-row = t>>2 (0..63), 4x16B swizzled cols ----
    const int br = tid >> 2;
    const int cg = tid & 3;
    const __half* pv = gB + (size_t)br * HW + cg * 32;
    uint32_t bswo[4];
#pragma unroll
    for (int j = 0; j < 4; ++j) {
        const int cc = cg * 4 + j;       // 16B col 0..15
        bswo[j] = ATILEB + (uint32_t)br * 256 + ((uint32_t)(cc ^ (br & 7)) << 4);
    }

#define LOAD_TILE(stage, ch) do {                                             \
        const uint32_t _s = sb + (stage) * STAGEB;                            \
        const __half* _pa = pa + (size_t)(ch) * BKH;                          \
        cp_async16(_s + aswo[0], _pa);                                        \
        cp_async16(_s + aswo[1], _pa + 8);                                    \
        cp_async16(_s + aswo[2], _pa + 16);                                   \
        cp_async16(_s + aswo[3], _pa + 24);                                   \
        const __half* _pv = pv + (size_t)(ch) * BKH * HW;                     \
        cp_async16(_s + bswo[0], _pv);                                        \
        cp_async16(_s + bswo[1], _pv + 8);                                    \
        cp_async16(_s + bswo[2], _pv + 16);                                   \
        cp_async16(_s + bswo[3], _pv + 24);                                   \
    } while (0)

    // ---- ldmatrix offsets ----
    const int wm = (wid >> 2) * 64;      // warp m (o): 0 / 64
    const int wn = (wid & 3) * 32;       // warp n (p): 0..96
    uint32_t aOff[4];
#pragma unroll
    for (int mt = 0; mt < 4; ++mt) {
        const uint32_t off = (uint32_t)((wm + mt * 16 + (lane & 15)) * 128
                                        + ((lane & 16) ? 16 : 0));
        aOff[mt] = SWZ128(off);
    }
    const int mIdx = lane >> 3;
    const int koff = ((mIdx & 1) << 3) + (lane & 7);
    const int cc0  = (wn >> 3) + (mIdx >> 1);
    const int cc1  = cc0 + 2;
    const uint32_t bO0 = ATILEB + (uint32_t)koff * 256 + ((uint32_t)(cc0 ^ (koff & 7)) << 4);
    const uint32_t bO1 = ATILEB + (uint32_t)koff * 256 + ((uint32_t)(cc1 ^ (koff & 7)) << 4);

#define LOAD_FRAGS(buf, sbase, s) do {                                        \
        LDSM4(afr[buf][0], (sbase) + (aOff[0] ^ ((s) << 5)));                 \
        LDSM4(afr[buf][1], (sbase) + (aOff[1] ^ ((s) << 5)));                 \
        LDSM4(afr[buf][2], (sbase) + (aOff[2] ^ ((s) << 5)));                 \
        LDSM4(afr[buf][3], (sbase) + (aOff[3] ^ ((s) << 5)));                 \
        LDSM4T(b0f[buf], (sbase) + bO0 + (s) * 4096);                         \
        LDSM4T(b1f[buf], (sbase) + bO1 + (s) * 4096);                         \
    } while (0)

    float c[16][4];
#pragma unroll
    for (int i = 0; i < 16; ++i)
#pragma unroll
        for (int j = 0; j < 4; ++j) c[i][j] = 0.f;

    uint32_t afr[2][4][4], b0f[2][4], b1f[2][4];

    LOAD_TILE(0, 0); CP_COMMIT();
    LOAD_TILE(1, 1); CP_COMMIT();

    int stage = 0;
    for (int ch = 0; ch < NCH; ++ch) {
        if (ch + 2 < NCH) {
            const int ns = (stage + 2 >= NSTAGE) ? stage + 2 - NSTAGE : stage + 2;
            LOAD_TILE(ns, ch + 2);
        }
        CP_COMMIT();
        CP_WAIT(2);
        __syncthreads();

        const uint32_t sbase = sb + stage * STAGEB;
        LOAD_FRAGS(0, sbase, 0);
#pragma unroll
        for (int s = 0; s < 4; ++s) {
            const int cur = s & 1;
            if (s < 3) LOAD_FRAGS(cur ^ 1, sbase, s + 1);
#pragma unroll
            for (int mt = 0; mt < 4; ++mt) {
                mma16816(c[mt * 4 + 0], afr[cur][mt], &b0f[cur][0]);
                mma16816(c[mt * 4 + 1], afr[cur][mt], &b0f[cur][2]);
                mma16816(c[mt * 4 + 2], afr[cur][mt], &b1f[cur][0]);
                mma16816(c[mt * 4 + 3], afr[cur][mt], &b1f[cur][2]);
            }
        }
        __syncthreads();
        stage = (stage + 1 >= NSTAGE) ? 0 : stage + 1;
    }

    // epilogue
    const int qr = lane >> 2;
    const int qc = lane & 3;
#pragma unroll
    for (int mt = 0; mt < 4; ++mt) {
#pragma unroll
        for (int nt = 0; nt < 4; ++nt) {
            const int o = m0 + wm + mt * 16 + qr;
            const int p = n0 + wn + nt * 8 + 2 * qc;
            float* o0 = out + ((size_t)(b * CO + o)) * HW + p;
            float2 v0; v0.x = c[mt * 4 + nt][0]; v0.y = c[mt * 4 + nt][1];
            *(float2*)o0 = v0;
            float2 v1; v1.x = c[mt * 4 + nt][2]; v1.y = c[mt * 4 + nt][3];
            *(float2*)(o0 + 8 * HW) = v1;
        }
    }
}

// ---------------------------------------------------------------------------
extern "C" void kernel_launch(void* const* d_in, const int* in_sizes, int n_in,
                              void* d_out, int out_size)
{
    const float* x   = (const float*)d_in[0];   // [2,256,64,64]
    const float* res = (const float*)d_in[1];   // [2,256,64,64]
    const float* ow  = (const float*)d_in[2];   // [18,256,3,3]
    const float* ob  = (const float*)d_in[3];   // [18]
    const float* mw  = (const float*)d_in[4];   // [9,256,3,3]
    const float* mb  = (const float*)d_in[5];   // [9]
    const float* rw  = (const float*)d_in[6];   // [256,256,3,3]
    float* out = (float*)d_out;                 // [2,256,64,64]

    static int smem_set = 0;
    if (!smem_set) {
        cudaFuncSetAttribute(gemm_mma_kernel,
                             cudaFuncAttributeMaxDynamicSharedMemorySize, GEMM_SMEM);
        smem_set = 1;
    }

    prep_w_kernel<<<CO * CK / 4 / 256, 256>>>(rw);
    conv_offmod_kernel<<<256, 128>>>(x, res, ow, mw);
    sample_kernel<<<dim3(HW / 32, BATCH), 288>>>(x, ob, mb);
    gemm_mma_kernel<<<dim3(HW / 128, CO / 128, BATCH), 256, GEMM_SMEM>>>(out);
}

// round 7
// speedup vs baseline: 3.2030x; 1.0094x over previous
#include <cuda_runtime.h>
#include <cuda_fp16.h>
#include <cstdint>
#include <math.h>

// Problem constants
#define BATCH 2
#define C 256
#define H 64
#define W 64
#define HW 4096
#define K2 9
#define CO 256
#define CK 2304        // C*K2
#define G 16           // channel groups for conv partial sums (16 ch each)

// Scratch (__device__ globals; allocation-free rule)
__device__ float  g_part[BATCH * G * 27 * HW];     // [b][g][o(27)][p]
__device__ __half g_vh[(size_t)BATCH * CK * HW];   // [b][ck][p]  p-contiguous fp16
__device__ __half g_wh[(size_t)CO * CK];           // W fp16, K-major rows of o

// ---------------------------------------------------------------------------
// helpers
// ---------------------------------------------------------------------------
__device__ __forceinline__ uint32_t smem_u32(const void* p) {
    uint32_t a;
    asm("{ .reg .u64 t; cvta.to.shared.u64 t, %1; cvt.u32.u64 %0, t; }" : "=r"(a) : "l"(p));
    return a;
}
__device__ __forceinline__ void cp_async16(uint32_t dst, const void* src) {
    asm volatile("cp.async.cg.shared.global [%0], [%1], 16;" :: "r"(dst), "l"(src));
}
#define CP_COMMIT() asm volatile("cp.async.commit_group;" ::: "memory")
#define CP_WAIT(n)  asm volatile("cp.async.wait_group %0;" :: "n"(n) : "memory")
#define SWZ128(off) ((off) ^ (((off) >> 3) & 0x70))

#define LDSM4(r, addr) \
    asm volatile("ldmatrix.sync.aligned.m8n8.x4.shared.b16 {%0,%1,%2,%3}, [%4];" \
        : "=r"((r)[0]), "=r"((r)[1]), "=r"((r)[2]), "=r"((r)[3]) : "r"(addr))
#define LDSM4T(r, addr) \
    asm volatile("ldmatrix.sync.aligned.m8n8.x4.trans.shared.b16 {%0,%1,%2,%3}, [%4];" \
        : "=r"((r)[0]), "=r"((r)[1]), "=r"((r)[2]), "=r"((r)[3]) : "r"(addr))

__device__ __forceinline__ void mma16816(float c[4], const uint32_t a[4], const uint32_t b[2]) {
    asm volatile(
        "mma.sync.aligned.m16n8k16.row.col.f32.f16.f16.f32 "
        "{%0,%1,%2,%3}, {%4,%5,%6,%7}, {%8,%9}, {%0,%1,%2,%3};"
        : "+f"(c[0]), "+f"(c[1]), "+f"(c[2]), "+f"(c[3])
        : "r"(a[0]), "r"(a[1]), "r"(a[2]), "r"(a[3]), "r"(b[0]), "r"(b[1]));
}

// ---------------------------------------------------------------------------
// Kernel 0: convert reg_w to fp16 (K-major rows of o)
// ---------------------------------------------------------------------------
__global__ __launch_bounds__(256)
void prep_w_kernel(const float* __restrict__ w)
{
    const int i = blockIdx.x * 256 + threadIdx.x;   // CO*CK/4 = 147456
    const float4 v = ((const float4*)w)[i];
    __half2* dst = (__half2*)(g_wh + (size_t)i * 4);
    dst[0] = __floats2half2_rn(v.x, v.y);
    dst[1] = __floats2half2_rn(v.z, v.w);
}

// ---------------------------------------------------------------------------
// Kernel 1: offset conv (18ch from residual) + mod conv (9ch from x).
// 4 pixels/thread (1x4 strip), two passes (res-outputs, then x-outputs),
// G=16 channel groups (16 ch each). 256 blocks x 128 threads.
// ---------------------------------------------------------------------------
__global__ __launch_bounds__(128)
void conv_offmod_kernel(const float* __restrict__ x,
                        const float* __restrict__ res,
                        const float* __restrict__ ow,   // [18][C][9]
                        const float* __restrict__ mw)   // [9][C][9]
{
    __shared__ __align__(16) float sw[16 * 27 * 12];    // 20.7 KB

    const int tid  = threadIdx.x;
    const int bidx = blockIdx.x;          // B*G*8 = 256 blocks
    const int pblk = bidx & 7;
    const int g    = (bidx >> 3) & (G - 1);
    const int b    = bidx >> 7;
    const int p    = pblk * 512 + tid * 4;    // 4 px per thread, same row
    const int h    = p >> 6;
    const int w    = p & 63;                   // multiple of 4

    const int cbase = g * 16;
    // stage weights for this group's 16 channels (all 27 outputs)
    for (int i = tid; i < 16 * 243; i += 128) {
        const int ci = i / 243;
        const int t  = i % 243;
        const int c  = cbase + ci;
        const int o  = t / 9;
        const int tt = t % 9;
        float wv;
        if (o < 18) wv = ow[(size_t)o * CK + c * 9 + tt];
        else        wv = mw[(size_t)(o - 18) * CK + c * 9 + tt];
        sw[ci * 324 + o * 12 + tt] = wv;
    }
    __syncthreads();

    float* outp = g_part + (size_t)(b * G + g) * 27 * HW;

    // ---------------- Pass A: 18 offset outputs from residual ----------------
    {
        float acc[18][4];
#pragma unroll
        for (int o = 0; o < 18; ++o)
#pragma unroll
            for (int j = 0; j < 4; ++j) acc[o][j] = 0.f;

        const float* rb = res + (size_t)b * C * HW;
        for (int ci = 0; ci < 16; ++ci) {
            const float* rc = rb + (size_t)(cbase + ci) * HW;
            float rv[18];   // 3 rows x 6 cols
#pragma unroll
            for (int r = 0; r < 3; ++r) {
                const int hh = h + r - 1;
                const bool vy = ((unsigned)hh < 64u);
#pragma unroll
                for (int s = 0; s < 6; ++s) {
                    const int ww = w + s - 1;
                    const bool v = vy && ((unsigned)ww < 64u);
                    rv[r * 6 + s] = v ? rc[hh * 64 + ww] : 0.f;
                }
            }
            const float* swc = sw + ci * 324;
#pragma unroll
            for (int o = 0; o < 18; ++o) {
                const float4 wA = *(const float4*)(swc + o * 12);
                const float4 wB = *(const float4*)(swc + o * 12 + 4);
                const float  w8 = swc[o * 12 + 8];
#pragma unroll
                for (int j = 0; j < 4; ++j) {
                    acc[o][j] += wA.x * rv[j]      + wA.y * rv[j + 1]  + wA.z * rv[j + 2]
                               + wA.w * rv[j + 6]  + wB.x * rv[j + 7]  + wB.y * rv[j + 8]
                               + wB.z * rv[j + 12] + wB.w * rv[j + 13] + w8  * rv[j + 14];
                }
            }
        }
#pragma unroll
        for (int o = 0; o < 18; ++o) {
            float4 v; v.x = acc[o][0]; v.y = acc[o][1]; v.z = acc[o][2]; v.w = acc[o][3];
            *(float4*)(outp + o * HW + p) = v;
        }
    }

    // ---------------- Pass B: 9 modulator outputs from x ----------------
    {
        float acc[9][4];
#pragma unroll
        for (int o = 0; o < 9; ++o)
#pragma unroll
            for (int j = 0; j < 4; ++j) acc[o][j] = 0.f;

        const float* xb = x + (size_t)b * C * HW;
        for (int ci = 0; ci < 16; ++ci) {
            const float* xc = xb + (size_t)(cbase + ci) * HW;
            float xv[18];
#pragma unroll
            for (int r = 0; r < 3; ++r) {
                const int hh = h + r - 1;
                const bool vy = ((unsigned)hh < 64u);
#pragma unroll
                for (int s = 0; s < 6; ++s) {
                    const int ww = w + s - 1;
                    const bool v = vy && ((unsigned)ww < 64u);
                    xv[r * 6 + s] = v ? xc[hh * 64 + ww] : 0.f;
                }
            }
            const float* swc = sw + ci * 324;
#pragma unroll
            for (int o = 0; o < 9; ++o) {
                const float4 wA = *(const float4*)(swc + (18 + o) * 12);
                const float4 wB = *(const float4*)(swc + (18 + o) * 12 + 4);
                const float  w8 = swc[(18 + o) * 12 + 8];
#pragma unroll
                for (int j = 0; j < 4; ++j) {
                    acc[o][j] += wA.x * xv[j]      + wA.y * xv[j + 1]  + wA.z * xv[j + 2]
                               + wA.w * xv[j + 6]  + wB.x * xv[j + 7]  + wB.y * xv[j + 8]
                               + wB.z * xv[j + 12] + wB.w * xv[j + 13] + w8  * xv[j + 14];
                }
            }
        }
#pragma unroll
        for (int o = 0; o < 9; ++o) {
            float4 v; v.x = acc[o][0]; v.y = acc[o][1]; v.z = acc[o][2]; v.w = acc[o][3];
            *(float4*)(outp + (18 + o) * HW + p) = v;
        }
    }
}

// ---------------------------------------------------------------------------
// Kernel 2: sampling. 288 threads: warp = tap k, lane = pixel. Each thread
// handles TWO pixels (p0+lane, p0+32+lane) -> 8 independent gathers per
// channel iteration (deep MLP). Registers-only setup, direct fp16 writes.
// ---------------------------------------------------------------------------
__global__ __launch_bounds__(288)
void sample_kernel(const float* __restrict__ x,
                   const float* __restrict__ ob,   // [18]
                   const float* __restrict__ mb)   // [9]
{
    const int tid  = threadIdx.x;
    const int lane = tid & 31;
    const int k    = tid >> 5;           // 0..8
    const int b    = blockIdx.y;
    const int p0   = blockIdx.x * 64;

    int   l[2][4];
    float wq[2][4];

    const float* pb = g_part + (size_t)b * G * 27 * HW;
    const float kdy = (float)(k / 3 - 1);
    const float kdx = (float)(k % 3 - 1);

#pragma unroll
    for (int t = 0; t < 2; ++t) {
        const int p = p0 + t * 32 + lane;
        const int h = p >> 6;
        const int w = p & 63;

        float dy   = ob[2 * k];
        float dx   = ob[2 * k + 1];
        float mraw = mb[k];
#pragma unroll
        for (int g = 0; g < G; ++g) {
            dy   += pb[(g * 27 + 2 * k)     * HW + p];
            dx   += pb[(g * 27 + 2 * k + 1) * HW + p];
            mraw += pb[(g * 27 + 18 + k)    * HW + p];
        }
        const float m = 2.f / (1.f + expf(-mraw));

        const float py = dy + (float)h + kdy;
        const float px = dx + (float)w + kdx;
        const float y0f = floorf(py), x0f = floorf(px);
        const float wy1 = py - y0f,  wx1 = px - x0f;
        const float wy0 = 1.f - wy1, wx0 = 1.f - wx1;
        const int y0 = (int)y0f, x0 = (int)x0f;
        const int y1 = y0 + 1,   x1 = x0 + 1;

        bool v; int yc, xc;
        v = ((unsigned)y0 < 64u) && ((unsigned)x0 < 64u);
        yc = min(max(y0, 0), 63); xc = min(max(x0, 0), 63);
        l[t][0] = yc * 64 + xc; wq[t][0] = v ? wy0 * wx0 * m : 0.f;
        v = ((unsigned)y0 < 64u) && ((unsigned)x1 < 64u);
        yc = min(max(y0, 0), 63); xc = min(max(x1, 0), 63);
        l[t][1] = yc * 64 + xc; wq[t][1] = v ? wy0 * wx1 * m : 0.f;
        v = ((unsigned)y1 < 64u) && ((unsigned)x0 < 64u);
        yc = min(max(y1, 0), 63); xc = min(max(x0, 0), 63);
        l[t][2] = yc * 64 + xc; wq[t][2] = v ? wy1 * wx0 * m : 0.f;
        v = ((unsigned)y1 < 64u) && ((unsigned)x1 < 64u);
        yc = min(max(y1, 0), 63); xc = min(max(x1, 0), 63);
        l[t][3] = yc * 64 + xc; wq[t][3] = v ? wy1 * wx1 * m : 0.f;
    }

    const float* xc = x + (size_t)b * C * HW;
    __half* dst0 = g_vh + ((size_t)b * CK + k) * HW + p0 + lane;

#pragma unroll 4
    for (int c = 0; c < C; ++c) {
        const float f0 = wq[0][0] * __ldg(xc + l[0][0]) + wq[0][1] * __ldg(xc + l[0][1])
                       + wq[0][2] * __ldg(xc + l[0][2]) + wq[0][3] * __ldg(xc + l[0][3]);
        const float f1 = wq[1][0] * __ldg(xc + l[1][0]) + wq[1][1] * __ldg(xc + l[1][1])
                       + wq[1][2] * __ldg(xc + l[1][2]) + wq[1][3] * __ldg(xc + l[1][3]);
        dst0[0]  = __float2half_rn(f0);
        dst0[32] = __float2half_rn(f1);
        xc   += HW;
        dst0 += (size_t)9 * HW;
    }
}

// ---------------------------------------------------------------------------
// Kernel 3: fp16 mma.sync GEMM (R6 version — at its HMMA issue bound).
// Tile 128(o) x 128(p), BK=64, 3-stage cp.async + reg double buffering.
// ---------------------------------------------------------------------------
#define BKH    64
#define ATILEB 16384
#define BTILEB 16384
#define STAGEB (ATILEB + BTILEB)
#define NSTAGE 3
#define NCH    (CK / BKH)                // 36
#define GEMM_SMEM (NSTAGE * STAGEB)      // 98304 B

__global__ __launch_bounds__(256)
void gemm_mma_kernel(float* __restrict__ out)
{
    extern __shared__ char smc[];
    const uint32_t sb = smem_u32(smc);

    const int tid  = threadIdx.x;
    const int lane = tid & 31;
    const int wid  = tid >> 5;
    const int b    = blockIdx.z;
    const int m0   = blockIdx.y * 128;   // o
    const int n0   = blockIdx.x * 128;   // p

    const __half* gA = g_wh + (size_t)m0 * CK;
    const __half* gB = g_vh + (size_t)b * CK * HW + n0;

    const int ar  = tid >> 1;
    const int seg = tid & 1;
    const __half* pa = gA + (size_t)ar * CK + seg * 32;
    uint32_t aswo[4];
#pragma unroll
    for (int j = 0; j < 4; ++j)
        aswo[j] = SWZ128((uint32_t)(ar * 128 + seg * 64 + j * 16));

    const int br = tid >> 2;
    const int cg = tid & 3;
    const __half* pv = gB + (size_t)br * HW + cg * 32;
    uint32_t bswo[4];
#pragma unroll
    for (int j = 0; j < 4; ++j) {
        const int cc = cg * 4 + j;
        bswo[j] = ATILEB + (uint32_t)br * 256 + ((uint32_t)(cc ^ (br & 7)) << 4);
    }

#define LOAD_TILE(stage, ch) do {                                             \
        const uint32_t _s = sb + (stage) * STAGEB;                            \
        const __half* _pa = pa + (size_t)(ch) * BKH;                          \
        cp_async16(_s + aswo[0], _pa);                                        \
        cp_async16(_s + aswo[1], _pa + 8);                                    \
        cp_async16(_s + aswo[2], _pa + 16);                                   \
        cp_async16(_s + aswo[3], _pa + 24);                                   \
        const __half* _pv = pv + (size_t)(ch) * BKH * HW;                     \
        cp_async16(_s + bswo[0], _pv);                                        \
        cp_async16(_s + bswo[1], _pv + 8);                                    \
        cp_async16(_s + bswo[2], _pv + 16);                                   \
        cp_async16(_s + bswo[3], _pv + 24);                                   \
    } while (0)

    const int wm = (wid >> 2) * 64;
    const int wn = (wid & 3) * 32;
    uint32_t aOff[4];
#pragma unroll
    for (int mt = 0; mt < 4; ++mt) {
        const uint32_t off = (uint32_t)((wm + mt * 16 + (lane & 15)) * 128
                                        + ((lane & 16) ? 16 : 0));
        aOff[mt] = SWZ128(off);
    }
    const int mIdx = lane >> 3;
    const int koff = ((mIdx & 1) << 3) + (lane & 7);
    const int cc0  = (wn >> 3) + (mIdx >> 1);
    const int cc1  = cc0 + 2;
    const uint32_t bO0 = ATILEB + (uint32_t)koff * 256 + ((uint32_t)(cc0 ^ (koff & 7)) << 4);
    const uint32_t bO1 = ATILEB + (uint32_t)koff * 256 + ((uint32_t)(cc1 ^ (koff & 7)) << 4);

#define LOAD_FRAGS(buf, sbase, s) do {                                        \
        LDSM4(afr[buf][0], (sbase) + (aOff[0] ^ ((s) << 5)));                 \
        LDSM4(afr[buf][1], (sbase) + (aOff[1] ^ ((s) << 5)));                 \
        LDSM4(afr[buf][2], (sbase) + (aOff[2] ^ ((s) << 5)));                 \
        LDSM4(afr[buf][3], (sbase) + (aOff[3] ^ ((s) << 5)));                 \
        LDSM4T(b0f[buf], (sbase) + bO0 + (s) * 4096);                         \
        LDSM4T(b1f[buf], (sbase) + bO1 + (s) * 4096);                         \
    } while (0)

    float c[16][4];
#pragma unroll
    for (int i = 0; i < 16; ++i)
#pragma unroll
        for (int j = 0; j < 4; ++j) c[i][j] = 0.f;

    uint32_t afr[2][4][4], b0f[2][4], b1f[2][4];

    LOAD_TILE(0, 0); CP_COMMIT();
    LOAD_TILE(1, 1); CP_COMMIT();

    int stage = 0;
    for (int ch = 0; ch < NCH; ++ch) {
        if (ch + 2 < NCH) {
            const int ns = (stage + 2 >= NSTAGE) ? stage + 2 - NSTAGE : stage + 2;
            LOAD_TILE(ns, ch + 2);
        }
        CP_COMMIT();
        CP_WAIT(2);
        __syncthreads();

        const uint32_t sbase = sb + stage * STAGEB;
        LOAD_FRAGS(0, sbase, 0);
#pragma unroll
        for (int s = 0; s < 4; ++s) {
            const int cur = s & 1;
            if (s < 3) LOAD_FRAGS(cur ^ 1, sbase, s + 1);
#pragma unroll
            for (int mt = 0; mt < 4; ++mt) {
                mma16816(c[mt * 4 + 0], afr[cur][mt], &b0f[cur][0]);
                mma16816(c[mt * 4 + 1], afr[cur][mt], &b0f[cur][2]);
                mma16816(c[mt * 4 + 2], afr[cur][mt], &b1f[cur][0]);
                mma16816(c[mt * 4 + 3], afr[cur][mt], &b1f[cur][2]);
            }
        }
        __syncthreads();
        stage = (stage + 1 >= NSTAGE) ? 0 : stage + 1;
    }

    const int qr = lane >> 2;
    const int qc = lane & 3;
#pragma unroll
    for (int mt = 0; mt < 4; ++mt) {
#pragma unroll
        for (int nt = 0; nt < 4; ++nt) {
            const int o = m0 + wm + mt * 16 + qr;
            const int p = n0 + wn + nt * 8 + 2 * qc;
            float* o0 = out + ((size_t)(b * CO + o)) * HW + p;
            float2 v0; v0.x = c[mt * 4 + nt][0]; v0.y = c[mt * 4 + nt][1];
            *(float2*)o0 = v0;
            float2 v1; v1.x = c[mt * 4 + nt][2]; v1.y = c[mt * 4 + nt][3];
            *(float2*)(o0 + 8 * HW) = v1;
        }
    }
}

// ---------------------------------------------------------------------------
extern "C" void kernel_launch(void* const* d_in, const int* in_sizes, int n_in,
                              void* d_out, int out_size)
{
    const float* x   = (const float*)d_in[0];   // [2,256,64,64]
    const float* res = (const float*)d_in[1];   // [2,256,64,64]
    const float* ow  = (const float*)d_in[2];   // [18,256,3,3]
    const float* ob  = (const float*)d_in[3];   // [18]
    const float* mw  = (const float*)d_in[4];   // [9,256,3,3]
    const float* mb  = (const float*)d_in[5];   // [9]
    const float* rw  = (const float*)d_in[6];   // [256,256,3,3]
    float* out = (float*)d_out;                 // [2,256,64,64]

    static int smem_set = 0;
    if (!smem_set) {
        cudaFuncSetAttribute(gemm_mma_kernel,
                             cudaFuncAttributeMaxDynamicSharedMemorySize, GEMM_SMEM);
        smem_set = 1;
    }

    prep_w_kernel<<<CO * CK / 4 / 256, 256>>>(rw);
    conv_offmod_kernel<<<256, 128>>>(x, res, ow, mw);
    sample_kernel<<<dim3(HW / 64, BATCH), 288>>>(x, ob, mb);
    gemm_mma_kernel<<<dim3(HW / 128, CO / 128, BATCH), 256, GEMM_SMEM>>>(out);
}